// round 2
// baseline (speedup 1.0000x reference)
#include <cuda_runtime.h>
#include <cstdint>

// Problem constants
#define B_ 4
#define L_ 2048
#define D_MODEL 1024
#define D_STATE 16
#define D_INNER 2048
#define D_CONV 4
#define DT_RANK 64
#define BL (B_ * L_)          // 8192 rows

// ---------------- scratch (static device globals; no allocs) ----------------
__device__ float g_xz[(size_t)BL * (2 * D_INNER)];   // in_proj output [8192, 4096]
__device__ float g_xs[(size_t)BL * D_INNER];         // conv+silu(x)   [8192, 2048]
__device__ float g_dbc[(size_t)BL * 96];             // x_proj output  [8192, 96]
__device__ float g_delta[(size_t)BL * D_INNER];      // softplus(dt)   [8192, 2048]
__device__ float g_y[(size_t)BL * D_INNER];          // scan output    [8192, 2048]

// ---------------- generic fp32 GEMM: C = act(A @ B + bias) ------------------
// A: M x K (row-major, lda), B: K x N (row-major, ldb), C: M x N (ldc)
// Requirements: K % 8 == 0, lda/ldb multiples of 4 (float4 alignment).
// act: 0 = none, 1 = softplus
__global__ __launch_bounds__(256) void sgemm128(
    const float* __restrict__ A, int lda,
    const float* __restrict__ B, int ldb,
    float* __restrict__ C, int ldc,
    int M, int N, int K,
    const float* __restrict__ bias, int act)
{
    __shared__ float As[8][128];   // transposed: As[k][m]
    __shared__ float Bs[8][128];   // Bs[k][n]

    const int t = threadIdx.x;
    const int row0 = blockIdx.y * 128;
    const int col0 = blockIdx.x * 128;

    // A-tile load mapping: 128 rows x 8 k, one float4 per thread
    const int a_r = t >> 1;            // 0..127
    const int a_c = (t & 1) * 4;       // 0 or 4
    // B-tile load mapping: 8 rows x 128 n, one float4 per thread
    const int b_r = t >> 5;            // 0..7
    const int b_c = (t & 31) * 4;      // 0..124

    const int ty = t >> 4, tx = t & 15;
    const int rm = ty * 8, rn = tx * 8;

    float acc[8][8];
#pragma unroll
    for (int i = 0; i < 8; i++)
#pragma unroll
        for (int j = 0; j < 8; j++) acc[i][j] = 0.f;

    for (int k0 = 0; k0 < K; k0 += 8) {
        // load A tile (transpose into As[k][m])
        {
            const int gm = row0 + a_r;
            const int gk = k0 + a_c;
            float4 va = make_float4(0.f, 0.f, 0.f, 0.f);
            if (gm < M)
                va = *reinterpret_cast<const float4*>(&A[(size_t)gm * lda + gk]);
            As[a_c + 0][a_r] = va.x;
            As[a_c + 1][a_r] = va.y;
            As[a_c + 2][a_r] = va.z;
            As[a_c + 3][a_r] = va.w;
        }
        // load B tile
        {
            const int gk = k0 + b_r;
            const int gn = col0 + b_c;
            float4 vb;
            if (gn + 3 < N) {
                vb = *reinterpret_cast<const float4*>(&B[(size_t)gk * ldb + gn]);
            } else {
                vb.x = (gn + 0) < N ? B[(size_t)gk * ldb + gn + 0] : 0.f;
                vb.y = (gn + 1) < N ? B[(size_t)gk * ldb + gn + 1] : 0.f;
                vb.z = (gn + 2) < N ? B[(size_t)gk * ldb + gn + 2] : 0.f;
                vb.w = (gn + 3) < N ? B[(size_t)gk * ldb + gn + 3] : 0.f;
            }
            *reinterpret_cast<float4*>(&Bs[b_r][b_c]) = vb;
        }
        __syncthreads();

#pragma unroll
        for (int kk = 0; kk < 8; kk++) {
            float ra[8], rb[8];
            *reinterpret_cast<float4*>(ra)     = *reinterpret_cast<const float4*>(&As[kk][rm]);
            *reinterpret_cast<float4*>(ra + 4) = *reinterpret_cast<const float4*>(&As[kk][rm + 4]);
            *reinterpret_cast<float4*>(rb)     = *reinterpret_cast<const float4*>(&Bs[kk][rn]);
            *reinterpret_cast<float4*>(rb + 4) = *reinterpret_cast<const float4*>(&Bs[kk][rn + 4]);
#pragma unroll
            for (int i = 0; i < 8; i++)
#pragma unroll
                for (int j = 0; j < 8; j++)
                    acc[i][j] = fmaf(ra[i], rb[j], acc[i][j]);
        }
        __syncthreads();
    }

    // epilogue
#pragma unroll
    for (int i = 0; i < 8; i++) {
        const int gm = row0 + rm + i;
        if (gm >= M) continue;
#pragma unroll
        for (int j = 0; j < 8; j++) {
            const int gn = col0 + rn + j;
            if (gn >= N) continue;
            float v = acc[i][j];
            if (bias) v += bias[gn];
            if (act == 1) v = (v > 20.f) ? v : log1pf(expf(v));
            C[(size_t)gm * ldc + gn] = v;
        }
    }
}

// ---------------- depthwise causal conv (k=4) + bias + SiLU -----------------
// x[b,l,d] = xz[(b*L+l)*4096 + d]   (first half of in_proj output)
// xs[b,l,d] = silu( sum_j w[d,j] * x[b,l-3+j,d] + bias[d] )
__global__ void conv_silu_kernel(const float* __restrict__ xz,
                                 const float* __restrict__ w,
                                 const float* __restrict__ bias,
                                 float* __restrict__ xs)
{
    const int idx = blockIdx.x * blockDim.x + threadIdx.x;
    if (idx >= B_ * L_ * D_INNER) return;
    const int d = idx & (D_INNER - 1);
    const int bl = idx >> 11;           // b*L + l
    const int l = bl & (L_ - 1);
    const int b = bl >> 11;

    const float* xbase = xz + (size_t)b * L_ * (2 * D_INNER) + d;  // stride 4096 over l
    const float w0 = w[d * 4 + 0];
    const float w1 = w[d * 4 + 1];
    const float w2 = w[d * 4 + 2];
    const float w3 = w[d * 4 + 3];

    float acc = bias[d];
    if (l >= 3) acc = fmaf(w0, xbase[(size_t)(l - 3) * (2 * D_INNER)], acc);
    if (l >= 2) acc = fmaf(w1, xbase[(size_t)(l - 2) * (2 * D_INNER)], acc);
    if (l >= 1) acc = fmaf(w2, xbase[(size_t)(l - 1) * (2 * D_INNER)], acc);
    acc = fmaf(w3, xbase[(size_t)l * (2 * D_INNER)], acc);

    xs[idx] = acc * (1.f / (1.f + __expf(-acc)));
}

// ---------------- selective scan + gating fused ------------------------------
// 16 lanes per (b,d) channel; lane n owns state n. Per step:
//   h = exp(dt*A[d,n])*h + dt*B[l,n]*x ;  y = sum_n h*C[l,n]
// then y = (y + x*D[d]) * silu(res) written by lane 0.
__global__ __launch_bounds__(256) void scan_kernel(
    const float* __restrict__ delta,   // [B,L,D_INNER]
    const float* __restrict__ dbc,     // [B,L,96]
    const float* __restrict__ xs,      // [B,L,D_INNER]
    const float* __restrict__ xz,      // [B,L,4096] (res = cols 2048..4095)
    const float* __restrict__ A_log,   // [D_INNER,16]
    const float* __restrict__ Dvec,    // [D_INNER]
    const float* __restrict__ hiddens, // [B,D_INNER,16]
    float* __restrict__ ybuf)          // [B,L,D_INNER]
{
    const int tid = blockIdx.x * blockDim.x + threadIdx.x;
    const int n = tid & 15;
    const int g = tid >> 4;            // 0 .. B*D_INNER-1
    const int b = g >> 11;
    const int d = g & (D_INNER - 1);

    const float a = -__expf(A_log[d * D_STATE + n]);
    float h = hiddens[((size_t)b * D_INNER + d) * D_STATE + n];
    const float Dd = Dvec[d];

    const float* dlt  = delta + (size_t)b * L_ * D_INNER + d;
    const float* xp   = xs    + (size_t)b * L_ * D_INNER + d;
    const float* dbcp = dbc   + (size_t)b * L_ * 96;
    const float* resp = xz    + (size_t)b * L_ * (2 * D_INNER) + D_INNER + d;
    float*       yp   = ybuf  + (size_t)b * L_ * D_INNER + d;

    for (int l = 0; l < L_; ++l) {
        const float dt = dlt[(size_t)l * D_INNER];
        const float xv = xp[(size_t)l * D_INNER];
        const float Bv = dbcp[l * 96 + DT_RANK + n];
        const float Cv = dbcp[l * 96 + DT_RANK + D_STATE + n];

        const float dA = __expf(dt * a);
        h = fmaf(dA, h, dt * Bv * xv);

        float s = h * Cv;
        s += __shfl_xor_sync(0xffffffffu, s, 1);
        s += __shfl_xor_sync(0xffffffffu, s, 2);
        s += __shfl_xor_sync(0xffffffffu, s, 4);
        s += __shfl_xor_sync(0xffffffffu, s, 8);

        if (n == 0) {
            const float rv = resp[(size_t)l * (2 * D_INNER)];
            float y = fmaf(xv, Dd, s);
            y *= rv * (1.f / (1.f + __expf(-rv)));
            yp[(size_t)l * D_INNER] = y;
        }
    }
}

// ---------------- launch ------------------------------------------------------
extern "C" void kernel_launch(void* const* d_in, const int* in_sizes, int n_in,
                              void* d_out, int out_size)
{
    const float* u          = (const float*)d_in[0];
    const float* hiddens    = (const float*)d_in[1];
    const float* in_proj_w  = (const float*)d_in[2];
    const float* conv_w     = (const float*)d_in[3];
    const float* conv_b     = (const float*)d_in[4];
    const float* x_proj_w   = (const float*)d_in[5];
    const float* dt_proj_w  = (const float*)d_in[6];
    const float* dt_proj_b  = (const float*)d_in[7];
    const float* A_log      = (const float*)d_in[8];
    const float* Dvec       = (const float*)d_in[9];
    const float* out_proj_w = (const float*)d_in[10];
    float* out = (float*)d_out;

    float *xz, *xs, *dbc, *delta, *ybuf;
    cudaGetSymbolAddress((void**)&xz, g_xz);
    cudaGetSymbolAddress((void**)&xs, g_xs);
    cudaGetSymbolAddress((void**)&dbc, g_dbc);
    cudaGetSymbolAddress((void**)&delta, g_delta);
    cudaGetSymbolAddress((void**)&ybuf, g_y);

    // 1) in_proj: xz[8192,4096] = u[8192,1024] @ W[1024,4096]
    sgemm128<<<dim3((2 * D_INNER) / 128, BL / 128), 256>>>(
        u, D_MODEL, in_proj_w, 2 * D_INNER, xz, 2 * D_INNER,
        BL, 2 * D_INNER, D_MODEL, nullptr, 0);

    // 2) conv + bias + silu -> xs
    {
        const int total = B_ * L_ * D_INNER;
        conv_silu_kernel<<<(total + 255) / 256, 256>>>(xz, conv_w, conv_b, xs);
    }

    // 3) x_proj: dbc[8192,96] = xs @ W[2048,96]
    sgemm128<<<dim3(1, BL / 128), 256>>>(
        xs, D_INNER, x_proj_w, 96, dbc, 96,
        BL, 96, D_INNER, nullptr, 0);

    // 4) dt_proj + softplus: delta[8192,2048] = softplus(dbc[:, :64] @ W[64,2048] + b)
    sgemm128<<<dim3(D_INNER / 128, BL / 128), 256>>>(
        dbc, 96, dt_proj_w, D_INNER, delta, D_INNER,
        BL, D_INNER, DT_RANK, dt_proj_b, 1);

    // 5) selective scan + D skip + silu(res) gating -> ybuf
    scan_kernel<<<(B_ * D_INNER * D_STATE) / 256, 256>>>(
        delta, dbc, xs, xz, A_log, Dvec, hiddens, ybuf);

    // 6) out_proj: out[8192,1024] = ybuf @ W[2048,1024]
    sgemm128<<<dim3(D_MODEL / 128, BL / 128), 256>>>(
        ybuf, D_INNER, out_proj_w, D_MODEL, out, D_MODEL,
        BL, D_MODEL, D_INNER, nullptr, 0);
}

// round 4
// speedup vs baseline: 1.0529x; 1.0529x over previous
#include <cuda_runtime.h>
#include <cstdint>

// Problem constants
#define B_ 4
#define L_ 2048
#define D_MODEL 1024
#define D_STATE 16
#define D_INNER 2048
#define D_CONV 4
#define DT_RANK 64
#define BL (B_ * L_)          // 8192 rows

// ---------------- scratch (static device globals; no allocs) ----------------
__device__ float g_xz[(size_t)BL * (2 * D_INNER)];   // in_proj output [8192, 4096]
__device__ float g_xs[(size_t)BL * D_INNER];         // conv+silu(x)   [8192, 2048]
__device__ float g_dbc[(size_t)BL * 96];             // x_proj output  [8192, 96]
__device__ float g_delta[(size_t)BL * D_INNER];      // softplus(dt)   [8192, 2048]
__device__ float g_y[(size_t)BL * D_INNER];          // scan output    [8192, 2048]

// ---------------- double-buffered fp32 GEMM -----------------------------------
// C[M,N] = act(A[M,K] @ B[K,N] (+ bias)),  all row-major.
// Template: block tile BM x BN, k-tile BK, per-thread TM x TN.
// Assumes M % BM == 0, N % BN == 0, K % BK == 0 (instantiated per exact shape).
// ACT: 0 = none, 1 = bias + softplus
template<int BM, int BN, int BK, int TM, int TN, int ACT>
__global__ __launch_bounds__((BM / TM) * (BN / TN), 2)
void gemm_db(const float* __restrict__ A, int lda,
             const float* __restrict__ B, int ldb,
             float* __restrict__ C, int ldc,
             int K, const float* __restrict__ bias)
{
    constexpr int NT = (BM / TM) * (BN / TN);
    constexpr int A4 = BM * BK / 4;        // float4 loads for A tile
    constexpr int B4 = BK * BN / 4;        // float4 loads for B tile
    constexpr int LA = (A4 + NT - 1) / NT;
    constexpr int LB = (B4 + NT - 1) / NT;

    __shared__ float As[2][BK][BM];        // transposed: As[k][m]
    __shared__ float Bs[2][BK][BN];        // Bs[k][n]

    const int tid  = threadIdx.x;
    const int row0 = blockIdx.y * BM;
    const int col0 = blockIdx.x * BN;

    const int tx = tid % (BN / TN);
    const int ty = tid / (BN / TN);
    const int rm = ty * TM;
    const int rn = tx * TN;

    float4 pa[LA];
    float4 pb[LB];

    float acc[TM][TN];
#pragma unroll
    for (int i = 0; i < TM; i++)
#pragma unroll
        for (int j = 0; j < TN; j++) acc[i][j] = 0.f;

    // ---- tile load helpers (LDG into regs / STS into smem) ----
    auto ldA = [&](int k0) {
#pragma unroll
        for (int i = 0; i < LA; i++) {
            const int idx = tid + i * NT;
            if ((A4 % NT == 0) || idx < A4) {
                const int m  = idx / (BK / 4);
                const int kq = (idx % (BK / 4)) * 4;
                pa[i] = *reinterpret_cast<const float4*>(
                    &A[(size_t)(row0 + m) * lda + k0 + kq]);
            }
        }
    };
    auto ldB = [&](int k0) {
#pragma unroll
        for (int i = 0; i < LB; i++) {
            const int idx = tid + i * NT;
            if ((B4 % NT == 0) || idx < B4) {
                const int kr = idx / (BN / 4);
                const int nq = (idx % (BN / 4)) * 4;
                pb[i] = *reinterpret_cast<const float4*>(
                    &B[(size_t)(k0 + kr) * ldb + col0 + nq]);
            }
        }
    };
    auto stA = [&](int buf) {
#pragma unroll
        for (int i = 0; i < LA; i++) {
            const int idx = tid + i * NT;
            if ((A4 % NT == 0) || idx < A4) {
                const int m  = idx / (BK / 4);
                const int kq = (idx % (BK / 4)) * 4;
                As[buf][kq + 0][m] = pa[i].x;
                As[buf][kq + 1][m] = pa[i].y;
                As[buf][kq + 2][m] = pa[i].z;
                As[buf][kq + 3][m] = pa[i].w;
            }
        }
    };
    auto stB = [&](int buf) {
#pragma unroll
        for (int i = 0; i < LB; i++) {
            const int idx = tid + i * NT;
            if ((B4 % NT == 0) || idx < B4) {
                const int kr = idx / (BN / 4);
                const int nq = (idx % (BN / 4)) * 4;
                *reinterpret_cast<float4*>(&Bs[buf][kr][nq]) = pb[i];
            }
        }
    };

    // ---- prologue: fill buffer 0 ----
    ldA(0); ldB(0);
    stA(0); stB(0);
    __syncthreads();

    const int T = K / BK;
    for (int t = 0; t < T; t++) {
        const int cur = t & 1;

        // prefetch next tile while computing current
        if (t + 1 < T) { ldA((t + 1) * BK); ldB((t + 1) * BK); }

#pragma unroll
        for (int kk = 0; kk < BK; kk++) {
            float ra[TM], rb[TN];
            if constexpr (TM % 4 == 0) {
#pragma unroll
                for (int i = 0; i < TM; i += 4)
                    *reinterpret_cast<float4*>(&ra[i]) =
                        *reinterpret_cast<const float4*>(&As[cur][kk][rm + i]);
            } else {
#pragma unroll
                for (int i = 0; i < TM; i++) ra[i] = As[cur][kk][rm + i];
            }
            if constexpr (TN % 4 == 0) {
#pragma unroll
                for (int j = 0; j < TN; j += 4)
                    *reinterpret_cast<float4*>(&rb[j]) =
                        *reinterpret_cast<const float4*>(&Bs[cur][kk][rn + j]);
            } else {
#pragma unroll
                for (int j = 0; j < TN; j++) rb[j] = Bs[cur][kk][rn + j];
            }
#pragma unroll
            for (int i = 0; i < TM; i++)
#pragma unroll
                for (int j = 0; j < TN; j++)
                    acc[i][j] = fmaf(ra[i], rb[j], acc[i][j]);
        }

        if (t + 1 < T) {
            stA(cur ^ 1); stB(cur ^ 1);
            __syncthreads();
        }
    }

    // ---- epilogue ----
#pragma unroll
    for (int i = 0; i < TM; i++) {
        const int gm = row0 + rm + i;
        float* crow = &C[(size_t)gm * ldc + col0 + rn];
#pragma unroll
        for (int j = 0; j < TN; j++) {
            float v = acc[i][j];
            if (ACT == 1) {
                v += bias[col0 + rn + j];
                v = (v > 20.f) ? v : log1pf(expf(v));
            }
            crow[j] = v;
        }
    }
}

// ---------------- depthwise causal conv (k=4) + bias + SiLU -----------------
__global__ void conv_silu_kernel(const float* __restrict__ xz,
                                 const float* __restrict__ w,
                                 const float* __restrict__ bias,
                                 float* __restrict__ xs)
{
    const int idx = blockIdx.x * blockDim.x + threadIdx.x;
    if (idx >= B_ * L_ * D_INNER) return;
    const int d  = idx & (D_INNER - 1);
    const int bl = idx >> 11;           // b*L + l
    const int l  = bl & (L_ - 1);
    const int b  = bl >> 11;

    const float* xbase = xz + (size_t)b * L_ * (2 * D_INNER) + d;
    const float w0 = w[d * 4 + 0];
    const float w1 = w[d * 4 + 1];
    const float w2 = w[d * 4 + 2];
    const float w3 = w[d * 4 + 3];

    float acc = bias[d];
    if (l >= 3) acc = fmaf(w0, xbase[(size_t)(l - 3) * (2 * D_INNER)], acc);
    if (l >= 2) acc = fmaf(w1, xbase[(size_t)(l - 2) * (2 * D_INNER)], acc);
    if (l >= 1) acc = fmaf(w2, xbase[(size_t)(l - 1) * (2 * D_INNER)], acc);
    acc = fmaf(w3, xbase[(size_t)l * (2 * D_INNER)], acc);

    xs[idx] = acc * (1.f / (1.f + __expf(-acc)));
}

// ---------------- selective scan + gating fused ------------------------------
__global__ __launch_bounds__(256) void scan_kernel(
    const float* __restrict__ delta,   // [B,L,D_INNER]
    const float* __restrict__ dbc,     // [B,L,96]
    const float* __restrict__ xs,      // [B,L,D_INNER]
    const float* __restrict__ xz,      // [B,L,4096] (res = cols 2048..4095)
    const float* __restrict__ A_log,   // [D_INNER,16]
    const float* __restrict__ Dvec,    // [D_INNER]
    const float* __restrict__ hiddens, // [B,D_INNER,16]
    float* __restrict__ ybuf)          // [B,L,D_INNER]
{
    const int tid = blockIdx.x * blockDim.x + threadIdx.x;
    const int n = tid & 15;
    const int g = tid >> 4;            // 0 .. B*D_INNER-1
    const int b = g >> 11;
    const int d = g & (D_INNER - 1);

    const float a = -__expf(A_log[d * D_STATE + n]);
    float h = hiddens[((size_t)b * D_INNER + d) * D_STATE + n];
    const float Dd = Dvec[d];

    const float* dlt  = delta + (size_t)b * L_ * D_INNER + d;
    const float* xp   = xs    + (size_t)b * L_ * D_INNER + d;
    const float* dbcp = dbc   + (size_t)b * L_ * 96;
    const float* resp = xz    + (size_t)b * L_ * (2 * D_INNER) + D_INNER + d;
    float*       yp   = ybuf  + (size_t)b * L_ * D_INNER + d;

    for (int l = 0; l < L_; ++l) {
        const float dt = dlt[(size_t)l * D_INNER];
        const float xv = xp[(size_t)l * D_INNER];
        const float Bv = dbcp[l * 96 + DT_RANK + n];
        const float Cv = dbcp[l * 96 + DT_RANK + D_STATE + n];

        const float dA = __expf(dt * a);
        h = fmaf(dA, h, dt * Bv * xv);

        float s = h * Cv;
        s += __shfl_xor_sync(0xffffffffu, s, 1);
        s += __shfl_xor_sync(0xffffffffu, s, 2);
        s += __shfl_xor_sync(0xffffffffu, s, 4);
        s += __shfl_xor_sync(0xffffffffu, s, 8);

        if (n == 0) {
            const float rv = resp[(size_t)l * (2 * D_INNER)];
            float y = fmaf(xv, Dd, s);
            y *= rv * (1.f / (1.f + __expf(-rv)));
            yp[(size_t)l * D_INNER] = y;
        }
    }
}

// ---------------- launch ------------------------------------------------------
extern "C" void kernel_launch(void* const* d_in, const int* in_sizes, int n_in,
                              void* d_out, int out_size)
{
    const float* u          = (const float*)d_in[0];
    const float* hiddens    = (const float*)d_in[1];
    const float* in_proj_w  = (const float*)d_in[2];
    const float* conv_w     = (const float*)d_in[3];
    const float* conv_b     = (const float*)d_in[4];
    const float* x_proj_w   = (const float*)d_in[5];
    const float* dt_proj_w  = (const float*)d_in[6];
    const float* dt_proj_b  = (const float*)d_in[7];
    const float* A_log      = (const float*)d_in[8];
    const float* Dvec       = (const float*)d_in[9];
    const float* out_proj_w = (const float*)d_in[10];
    float* out = (float*)d_out;

    float *xz, *xs, *dbc, *delta, *ybuf;
    cudaGetSymbolAddress((void**)&xz, g_xz);
    cudaGetSymbolAddress((void**)&xs, g_xs);
    cudaGetSymbolAddress((void**)&dbc, g_dbc);
    cudaGetSymbolAddress((void**)&delta, g_delta);
    cudaGetSymbolAddress((void**)&ybuf, g_y);

    // 1) in_proj: xz[8192,4096] = u[8192,1024] @ W[1024,4096]
    gemm_db<128, 128, 16, 8, 8, 0><<<dim3((2 * D_INNER) / 128, BL / 128), 256>>>(
        u, D_MODEL, in_proj_w, 2 * D_INNER, xz, 2 * D_INNER, D_MODEL, nullptr);

    // 2) conv + bias + silu -> xs
    {
        const int total = B_ * L_ * D_INNER;
        conv_silu_kernel<<<(total + 255) / 256, 256>>>(xz, conv_w, conv_b, xs);
    }

    // 3) x_proj: dbc[8192,96] = xs @ W[2048,96]   (BM=64 tiles -> 128 blocks)
    gemm_db<64, 96, 16, 4, 6, 0><<<dim3(1, BL / 64), 256>>>(
        xs, D_INNER, x_proj_w, 96, dbc, 96, D_INNER, nullptr);

    // 4) dt_proj + softplus: delta[8192,2048] = softplus(dbc[:, :64] @ W[64,2048] + b)
    gemm_db<128, 128, 16, 8, 8, 1><<<dim3(D_INNER / 128, BL / 128), 256>>>(
        dbc, 96, dt_proj_w, D_INNER, delta, D_INNER, DT_RANK, dt_proj_b);

    // 5) selective scan + D skip + silu(res) gating -> ybuf
    scan_kernel<<<(B_ * D_INNER * D_STATE) / 256, 256>>>(
        delta, dbc, xs, xz, A_log, Dvec, hiddens, ybuf);

    // 6) out_proj: out[8192,1024] = ybuf @ W[2048,1024]
    gemm_db<128, 128, 16, 8, 8, 0><<<dim3(D_MODEL / 128, BL / 128), 256>>>(
        ybuf, D_INNER, out_proj_w, D_MODEL, out, D_MODEL, D_INNER, nullptr);
}

// round 10
// speedup vs baseline: 1.4055x; 1.3349x over previous
#include <cuda_runtime.h>
#include <cuda_bf16.h>
#include <cstdint>

// Problem constants
#define B_ 4
#define L_ 2048
#define D_MODEL 1024
#define D_STATE 16
#define D_INNER 2048
#define D_CONV 4
#define DT_RANK 64
#define BL (B_ * L_)          // 8192 rows

typedef __nv_bfloat16 bf16;

// ---------------- scratch (static device globals; no allocs) ----------------
__device__ float g_xz   [(size_t)BL * 4096];      // in_proj out fp32
__device__ float g_xs   [(size_t)BL * 2048];      // conv+silu fp32 (for scan)
__device__ bf16  g_xs3  [(size_t)BL * 6144];      // conv+silu split bf16 (x_proj A)
__device__ bf16  g_u3   [(size_t)BL * 3072];      // u split bf16 (in_proj A)
__device__ float g_dbc  [(size_t)BL * 96];        // x_proj out fp32
__device__ bf16  g_dt3  [(size_t)BL * 192];       // dbc[:, :64] split bf16 (dt_proj A)
__device__ float g_delta[(size_t)BL * 2048];      // softplus(dt_proj) fp32
__device__ bf16  g_y3   [(size_t)BL * 6144];      // scan out split bf16 (out_proj A)
__device__ bf16  g_w3_in [(size_t)4096 * 3072];   // in_proj_w  -> [N,3K]
__device__ bf16  g_w3_xp [(size_t)128  * 6144];   // x_proj_w   -> [128(pad),3K]
__device__ bf16  g_w3_dt [(size_t)2048 * 192];    // dt_proj_w  -> [N,3K]
__device__ bf16  g_w3_out[(size_t)1024 * 6144];   // out_proj_w -> [N,3K]

// ---------------- helpers -----------------------------------------------------
__device__ __forceinline__ uint32_t smem_u32(const void* p) {
    uint32_t a;
    asm("{ .reg .u64 t; cvta.to.shared.u64 t, %1; cvt.u32.u64 %0, t; }" : "=r"(a) : "l"(p));
    return a;
}
#define CP_ASYNC16(dst, src) \
    asm volatile("cp.async.cg.shared.global [%0], [%1], 16;" :: "r"(dst), "l"(src))
#define CP_COMMIT()  asm volatile("cp.async.commit_group;")
#define CP_WAIT1()   asm volatile("cp.async.wait_group 1;")
#define CP_WAIT0()   asm volatile("cp.async.wait_group 0;")

__device__ __forceinline__ void ldm_x4(uint32_t* r, uint32_t addr) {
    asm volatile("ldmatrix.sync.aligned.m8n8.x4.shared.b16 {%0,%1,%2,%3}, [%4];"
                 : "=r"(r[0]), "=r"(r[1]), "=r"(r[2]), "=r"(r[3]) : "r"(addr));
}
__device__ __forceinline__ void mma16816(float* c, const uint32_t* a, const uint32_t* b) {
    asm volatile(
        "mma.sync.aligned.m16n8k16.row.col.f32.bf16.bf16.f32 "
        "{%0,%1,%2,%3}, {%4,%5,%6,%7}, {%8,%9}, {%0,%1,%2,%3};"
        : "+f"(c[0]), "+f"(c[1]), "+f"(c[2]), "+f"(c[3])
        : "r"(a[0]), "r"(a[1]), "r"(a[2]), "r"(a[3]), "r"(b[0]), "r"(b[1]));
}

// ---------------- mma.sync split-bf16 GEMM ------------------------------------
// C[M, N] = act( A3[M, K3] @ B3[N, K3]^T ), both K-major bf16, fp32 out.
// Block tile 128x128, BK=32, 8 warps (warp tile 64x32), cp.async double buffer.
// M % 128 == 0, B3 has >= ceil(N,128)*128 rows (zero-padded), K3 % 32 == 0.
// ACT: 0 none, 1 bias+softplus
#define TILE_B 10240          // 128 rows * 80B padded stride
#define SSTR   80             // padded row stride in bytes (32 bf16 = 64B + 16B pad)

template<int ACT>
__global__ __launch_bounds__(256, 2)
void gemm_mma(const bf16* __restrict__ A3, const bf16* __restrict__ B3, int K3,
              float* __restrict__ C, int ldc, int ncols,
              const float* __restrict__ bias)
{
    __shared__ __align__(16) char smem[2][2 * TILE_B];   // [stage][A | B]

    const int tid  = threadIdx.x;
    const int wid  = tid >> 5;
    const int lane = tid & 31;
    const int wm   = wid >> 2;         // 0..1  (64 rows each)
    const int wn   = wid & 3;          // 0..3  (32 cols each)
    const int row0 = blockIdx.y * 128;
    const int col0 = blockIdx.x * 128;

    const uint32_t s0 = smem_u32(smem);

    // global->smem tile loader (cp.async), tile = A[128x32] + B[128x32] bf16
    auto load_tile = [&](int stage, int k0) {
        const uint32_t sA = s0 + stage * (2 * TILE_B);
        const uint32_t sB = sA + TILE_B;
#pragma unroll
        for (int p = 0; p < 2; p++) {
            const int idx = tid + p * 256;     // 0..511
            const int r = idx >> 2, c = idx & 3;
            CP_ASYNC16(sA + r * SSTR + c * 16,
                       A3 + (size_t)(row0 + r) * K3 + k0 + c * 8);
            CP_ASYNC16(sB + r * SSTR + c * 16,
                       B3 + (size_t)(col0 + r) * K3 + k0 + c * 8);
        }
        CP_COMMIT();
    };

    float acc[4][4][4];
#pragma unroll
    for (int mi = 0; mi < 4; mi++)
#pragma unroll
        for (int ni = 0; ni < 4; ni++)
#pragma unroll
            for (int q = 0; q < 4; q++) acc[mi][ni][q] = 0.f;

    const int T = K3 / 32;
    load_tile(0, 0);
    load_tile(1, 32);

    const int lr16 = lane & 15;        // ldmatrix row-within-16
    const int khv  = (lane >> 4) * 8;  // k half select (0 or 8)

    for (int t = 0; t < T; t++) {
        if (t == T - 1) { CP_WAIT0(); } else { CP_WAIT1(); }
        __syncthreads();

        const int cur = t & 1;
        const uint32_t sA = s0 + cur * (2 * TILE_B);
        const uint32_t sB = sA + TILE_B;

#pragma unroll
        for (int ks = 0; ks < 32; ks += 16) {
            uint32_t af[4][4], bf[4][2];
#pragma unroll
            for (int mi = 0; mi < 4; mi++) {
                const int row = wm * 64 + mi * 16 + lr16;
                ldm_x4(af[mi], sA + row * SSTR + (ks + khv) * 2);
            }
#pragma unroll
            for (int nh = 0; nh < 2; nh++) {
                uint32_t r[4];
                const int row = wn * 32 + nh * 16 + lr16;
                ldm_x4(r, sB + row * SSTR + (ks + khv) * 2);
                bf[2 * nh + 0][0] = r[0]; bf[2 * nh + 1][0] = r[1];
                bf[2 * nh + 0][1] = r[2]; bf[2 * nh + 1][1] = r[3];
            }
#pragma unroll
            for (int mi = 0; mi < 4; mi++)
#pragma unroll
                for (int ni = 0; ni < 4; ni++)
                    mma16816(acc[mi][ni], af[mi], bf[ni]);
        }

        __syncthreads();
        if (t + 2 < T) load_tile(cur, (t + 2) * 32);
    }

    // epilogue
    const int g  = lane >> 2;
    const int tt = lane & 3;
#pragma unroll
    for (int mi = 0; mi < 4; mi++) {
        const int rA = row0 + wm * 64 + mi * 16 + g;
        float* cr0 = C + (size_t)rA * ldc;
        float* cr1 = C + (size_t)(rA + 8) * ldc;
#pragma unroll
        for (int ni = 0; ni < 4; ni++) {
            const int cn = col0 + wn * 32 + ni * 8 + tt * 2;
#pragma unroll
            for (int q = 0; q < 4; q++) {
                const int col = cn + (q & 1);
                if (col >= ncols) continue;
                float v = acc[mi][ni][q];
                if (ACT == 1) {
                    v += bias[col];
                    v = (v > 20.f) ? v : log1pf(expf(v));
                }
                ((q < 2) ? cr0 : cr1)[col] = v;
            }
        }
    }
}

// ---------------- fp32 -> split bf16 converters -------------------------------
// activations: A[M,K] (lda) -> A3[M,3K] = [hi | lo | hi]
__global__ void cvt_act(const float* __restrict__ A, int lda, int K, bf16* __restrict__ A3)
{
    const size_t idx = (size_t)blockIdx.x * blockDim.x + threadIdx.x;
    if (idx >= (size_t)BL * K) return;
    const int m = idx / K, k = idx % K;
    const float v = A[(size_t)m * lda + k];
    const bf16 hi = __float2bfloat16(v);
    const bf16 lo = __float2bfloat16(v - __bfloat162float(hi));
    const size_t base = (size_t)m * 3 * K;
    A3[base + k] = hi; A3[base + K + k] = lo; A3[base + 2 * K + k] = hi;
}

// weights: B[K,N] (ldb) -> B3[Nrows,3K] = [hi | hi | lo], transposed, zero-pad n>=N
__global__ void cvt_wt(const float* __restrict__ B, int K, int N, int ldb,
                       bf16* __restrict__ B3, int Nrows)
{
    __shared__ float t[32][33];
    const int k0 = blockIdx.y * 32, n0 = blockIdx.x * 32;
    const int tx = threadIdx.x, ty = threadIdx.y;   // 32 x 8
    for (int i = ty; i < 32; i += 8) {
        const int k = k0 + i, n = n0 + tx;
        t[i][tx] = (k < K && n < N) ? B[(size_t)k * ldb + n] : 0.f;
    }
    __syncthreads();
    for (int i = ty; i < 32; i += 8) {
        const int n = n0 + i;
        if (n >= Nrows) continue;
        const int k = k0 + tx;
        const float v = t[tx][i];
        const bf16 hi = __float2bfloat16(v);
        const bf16 lo = __float2bfloat16(v - __bfloat162float(hi));
        const size_t base = (size_t)n * 3 * K;
        B3[base + k] = hi; B3[base + K + k] = hi; B3[base + 2 * K + k] = lo;
    }
}

// ---------------- depthwise causal conv (k=4) + bias + SiLU ------------------
__global__ void conv_silu_kernel(const float* __restrict__ xz,
                                 const float* __restrict__ w,
                                 const float* __restrict__ bias,
                                 float* __restrict__ xs, bf16* __restrict__ xs3)
{
    const int idx = blockIdx.x * blockDim.x + threadIdx.x;
    if (idx >= B_ * L_ * D_INNER) return;
    const int d  = idx & (D_INNER - 1);
    const int bl = idx >> 11;
    const int l  = bl & (L_ - 1);
    const int b  = bl >> 11;

    const float* xbase = xz + (size_t)b * L_ * 4096 + d;
    float acc = bias[d];
    if (l >= 3) acc = fmaf(w[d * 4 + 0], xbase[(size_t)(l - 3) * 4096], acc);
    if (l >= 2) acc = fmaf(w[d * 4 + 1], xbase[(size_t)(l - 2) * 4096], acc);
    if (l >= 1) acc = fmaf(w[d * 4 + 2], xbase[(size_t)(l - 1) * 4096], acc);
    acc = fmaf(w[d * 4 + 3], xbase[(size_t)l * 4096], acc);

    const float s = acc * (1.f / (1.f + __expf(-acc)));
    xs[idx] = s;
    const bf16 hi = __float2bfloat16(s);
    const bf16 lo = __float2bfloat16(s - __bfloat162float(hi));
    const size_t base = (size_t)bl * 6144;
    xs3[base + d] = hi; xs3[base + 2048 + d] = lo; xs3[base + 4096 + d] = hi;
}

// ---------------- selective scan + gating, split-bf16 output -----------------
__global__ __launch_bounds__(256) void scan_kernel(
    const float* __restrict__ delta, const float* __restrict__ dbc,
    const float* __restrict__ xs, const float* __restrict__ xz,
    const float* __restrict__ A_log, const float* __restrict__ Dvec,
    const float* __restrict__ hiddens, bf16* __restrict__ y3)
{
    const int tid = blockIdx.x * blockDim.x + threadIdx.x;
    const int n = tid & 15;
    const int g = tid >> 4;
    const int b = g >> 11;
    const int d = g & (D_INNER - 1);

    const float a = -__expf(A_log[d * D_STATE + n]);
    float h = hiddens[((size_t)b * D_INNER + d) * D_STATE + n];
    const float Dd = Dvec[d];

    const float* dlt  = delta + (size_t)b * L_ * D_INNER + d;
    const float* xp   = xs    + (size_t)b * L_ * D_INNER + d;
    const float* dbcp = dbc   + (size_t)b * L_ * 96;
    const float* resp = xz    + (size_t)b * L_ * 4096 + D_INNER + d;

    for (int l = 0; l < L_; ++l) {
        const float dt = dlt[(size_t)l * D_INNER];
        const float xv = xp[(size_t)l * D_INNER];
        const float Bv = dbcp[l * 96 + DT_RANK + n];
        const float Cv = dbcp[l * 96 + DT_RANK + D_STATE + n];

        const float dA = __expf(dt * a);
        h = fmaf(dA, h, dt * Bv * xv);

        float s = h * Cv;
        s += __shfl_xor_sync(0xffffffffu, s, 1);
        s += __shfl_xor_sync(0xffffffffu, s, 2);
        s += __shfl_xor_sync(0xffffffffu, s, 4);
        s += __shfl_xor_sync(0xffffffffu, s, 8);

        if (n == 0) {
            const float rv = resp[(size_t)l * 4096];
            float y = fmaf(xv, Dd, s);
            y *= rv * (1.f / (1.f + __expf(-rv)));
            const bf16 hi = __float2bfloat16(y);
            const bf16 lo = __float2bfloat16(y - __bfloat162float(hi));
            const size_t base = ((size_t)b * L_ + l) * 6144;
            y3[base + d] = hi; y3[base + 2048 + d] = lo; y3[base + 4096 + d] = hi;
        }
    }
}

// ---------------- launch ------------------------------------------------------
extern "C" void kernel_launch(void* const* d_in, const int* in_sizes, int n_in,
                              void* d_out, int out_size)
{
    const float* u          = (const float*)d_in[0];
    const float* hiddens    = (const float*)d_in[1];
    const float* in_proj_w  = (const float*)d_in[2];
    const float* conv_w     = (const float*)d_in[3];
    const float* conv_b     = (const float*)d_in[4];
    const float* x_proj_w   = (const float*)d_in[5];
    const float* dt_proj_w  = (const float*)d_in[6];
    const float* dt_proj_b  = (const float*)d_in[7];
    const float* A_log      = (const float*)d_in[8];
    const float* Dvec       = (const float*)d_in[9];
    const float* out_proj_w = (const float*)d_in[10];
    float* out = (float*)d_out;

    float *xz, *xs, *dbc, *delta;
    bf16 *u3, *xs3, *dt3, *y3, *w3_in, *w3_xp, *w3_dt, *w3_out;
    cudaGetSymbolAddress((void**)&xz, g_xz);
    cudaGetSymbolAddress((void**)&xs, g_xs);
    cudaGetSymbolAddress((void**)&dbc, g_dbc);
    cudaGetSymbolAddress((void**)&delta, g_delta);
    cudaGetSymbolAddress((void**)&u3, g_u3);
    cudaGetSymbolAddress((void**)&xs3, g_xs3);
    cudaGetSymbolAddress((void**)&dt3, g_dt3);
    cudaGetSymbolAddress((void**)&y3, g_y3);
    cudaGetSymbolAddress((void**)&w3_in, g_w3_in);
    cudaGetSymbolAddress((void**)&w3_xp, g_w3_xp);
    cudaGetSymbolAddress((void**)&w3_dt, g_w3_dt);
    cudaGetSymbolAddress((void**)&w3_out, g_w3_out);

    const dim3 tb(32, 8);

    // weight conversions (transposed, split)
    cvt_wt<<<dim3(4096 / 32, 1024 / 32), tb>>>(in_proj_w, 1024, 4096, 4096, w3_in, 4096);
    cvt_wt<<<dim3(128 / 32, 2048 / 32), tb>>>(x_proj_w, 2048, 96, 96, w3_xp, 128);
    cvt_wt<<<dim3(2048 / 32, 64 / 32), tb>>>(dt_proj_w, 64, 2048, 2048, w3_dt, 2048);
    cvt_wt<<<dim3(1024 / 32, 2048 / 32), tb>>>(out_proj_w, 2048, 1024, 1024, w3_out, 1024);

    // u -> split
    cvt_act<<<(int)(((size_t)BL * 1024 + 255) / 256), 256>>>(u, 1024, 1024, u3);

    // 1) in_proj: xz[8192,4096] = u3 @ w3_in^T   (K3 = 3072)
    gemm_mma<0><<<dim3(4096 / 128, BL / 128), 256>>>(
        u3, w3_in, 3072, xz, 4096, 4096, nullptr);

    // 2) conv + bias + silu -> xs (fp32) + xs3 (split)
    conv_silu_kernel<<<(B_ * L_ * D_INNER + 255) / 256, 256>>>(xz, conv_w, conv_b, xs, xs3);

    // 3) x_proj: dbc[8192,96] = xs3 @ w3_xp^T   (K3 = 6144, N padded to 128)
    gemm_mma<0><<<dim3(1, BL / 128), 256>>>(
        xs3, w3_xp, 6144, dbc, 96, 96, nullptr);

    // 3b) dbc[:, :64] -> split
    cvt_act<<<(int)(((size_t)BL * 64 + 255) / 256), 256>>>(dbc, 96, 64, dt3);

    // 4) dt_proj + softplus: delta[8192,2048]   (K3 = 192)
    gemm_mma<1><<<dim3(2048 / 128, BL / 128), 256>>>(
        dt3, w3_dt, 192, delta, 2048, 2048, dt_proj_b);

    // 5) selective scan + D skip + silu(res) gating -> y3 (split)
    scan_kernel<<<(B_ * D_INNER * D_STATE) / 256, 256>>>(
        delta, dbc, xs, xz, A_log, Dvec, hiddens, y3);

    // 6) out_proj: out[8192,1024] = y3 @ w3_out^T   (K3 = 6144)
    gemm_mma<0><<<dim3(1024 / 128, BL / 128), 256>>>(
        y3, w3_out, 6144, out, 1024, 1024, nullptr);
}

// round 12
// speedup vs baseline: 1.9812x; 1.4096x over previous
#include <cuda_runtime.h>
#include <cuda_bf16.h>
#include <cstdint>

// Problem constants
#define B_ 4
#define L_ 2048
#define D_MODEL 1024
#define D_STATE 16
#define D_INNER 2048
#define D_CONV 4
#define DT_RANK 64
#define BL (B_ * L_)          // 8192 rows

typedef __nv_bfloat16 bf16;

// ---------------- scratch (static device globals; no allocs) ----------------
__device__ float g_xz   [(size_t)BL * 4096];      // in_proj out fp32
__device__ float g_xs   [(size_t)BL * 2048];      // conv+silu fp32 (for scan)
__device__ bf16  g_xs3  [(size_t)BL * 6144];      // conv+silu split bf16 (x_proj A)
__device__ bf16  g_u3   [(size_t)BL * 3072];      // u split bf16 (in_proj A)
__device__ float g_dbc  [(size_t)BL * 96];        // x_proj out fp32
__device__ bf16  g_dt3  [(size_t)BL * 192];       // dbc[:, :64] split bf16 (dt_proj A)
__device__ float g_delta[(size_t)BL * 2048];      // softplus(dt_proj) fp32
__device__ bf16  g_y3   [(size_t)BL * 6144];      // scan out split bf16 (out_proj A)
__device__ bf16  g_w3_in [(size_t)4096 * 3072];   // in_proj_w  -> [N,3K]
__device__ bf16  g_w3_xp [(size_t)128  * 6144];   // x_proj_w   -> [128(pad),3K]
__device__ bf16  g_w3_dt [(size_t)2048 * 192];    // dt_proj_w  -> [N,3K]
__device__ bf16  g_w3_out[(size_t)1024 * 6144];   // out_proj_w -> [N,3K]

// ---------------- helpers -----------------------------------------------------
__device__ __forceinline__ uint32_t smem_u32(const void* p) {
    uint32_t a;
    asm("{ .reg .u64 t; cvta.to.shared.u64 t, %1; cvt.u32.u64 %0, t; }" : "=r"(a) : "l"(p));
    return a;
}
#define CP_ASYNC16(dst, src) \
    asm volatile("cp.async.cg.shared.global [%0], [%1], 16;" :: "r"(dst), "l"(src))
#define CP_COMMIT()  asm volatile("cp.async.commit_group;")
#define CP_WAIT1()   asm volatile("cp.async.wait_group 1;")
#define CP_WAIT0()   asm volatile("cp.async.wait_group 0;")

__device__ __forceinline__ void ldm_x4(uint32_t* r, uint32_t addr) {
    asm volatile("ldmatrix.sync.aligned.m8n8.x4.shared.b16 {%0,%1,%2,%3}, [%4];"
                 : "=r"(r[0]), "=r"(r[1]), "=r"(r[2]), "=r"(r[3]) : "r"(addr));
}
__device__ __forceinline__ void mma16816(float* c, const uint32_t* a, const uint32_t* b) {
    asm volatile(
        "mma.sync.aligned.m16n8k16.row.col.f32.bf16.bf16.f32 "
        "{%0,%1,%2,%3}, {%4,%5,%6,%7}, {%8,%9}, {%0,%1,%2,%3};"
        : "+f"(c[0]), "+f"(c[1]), "+f"(c[2]), "+f"(c[3])
        : "r"(a[0]), "r"(a[1]), "r"(a[2]), "r"(a[3]), "r"(b[0]), "r"(b[1]));
}

// ---------------- mma.sync split-bf16 GEMM ------------------------------------
// C[M, N] = act( A3[M, K3] @ B3[N, K3]^T ), both K-major bf16, fp32 out.
// Block tile 128x128, BK=64, 8 warps (warp tile 64x32), 3-stage cp.async
// pipeline with ONE barrier per k-tile. K3 % 64 == 0, T = K3/64 >= 3.
// ACT: 0 none, 1 bias+softplus
#define SSTR   144            // padded row stride bytes (64 bf16 = 128B + 16B pad)
#define MAT_B  (128 * SSTR)   // one matrix tile = 18432 B
#define STAGE_B (2 * MAT_B)   // A + B = 36864 B
#define GEMM_SMEM (3 * STAGE_B)   // 110592 B

template<int ACT>
__global__ __launch_bounds__(256, 2)
void gemm_mma(const bf16* __restrict__ A3, const bf16* __restrict__ B3, int K3,
              float* __restrict__ C, int ldc, int ncols,
              const float* __restrict__ bias)
{
    extern __shared__ __align__(16) char smem[];

    const int tid  = threadIdx.x;
    const int wid  = tid >> 5;
    const int lane = tid & 31;
    const int wm   = wid >> 2;         // 0..1  (64 rows each)
    const int wn   = wid & 3;          // 0..3  (32 cols each)
    const int row0 = blockIdx.y * 128;
    const int col0 = blockIdx.x * 128;

    const uint32_t s0 = smem_u32(smem);

    // per-thread fixed gmem/smem mapping for cp.async tile loads
    const int lr = tid >> 1;                 // 0..127 row
    const int lc = (tid & 1) * 4;            // 0 or 4 (16B chunks)
    const bf16* gA = A3 + (size_t)(row0 + lr) * K3 + lc * 8;
    const bf16* gB = B3 + (size_t)(col0 + lr) * K3 + lc * 8;
    const uint32_t sOffA = lr * SSTR + lc * 16;

    // tile = A[128x64] + B[128x64] bf16; each thread: 4 chunks A + 4 chunks B
    auto load_tile = [&](int stage, int k0) {
        const uint32_t sA = s0 + stage * STAGE_B + sOffA;
        const uint32_t sB = sA + MAT_B;
        const bf16* pA = gA + k0;
        const bf16* pB = gB + k0;
#pragma unroll
        for (int c = 0; c < 4; c++) {
            CP_ASYNC16(sA + c * 16, pA + c * 8);
            CP_ASYNC16(sB + c * 16, pB + c * 8);
        }
        CP_COMMIT();
    };

    float acc[4][4][4];
#pragma unroll
    for (int mi = 0; mi < 4; mi++)
#pragma unroll
        for (int ni = 0; ni < 4; ni++)
#pragma unroll
            for (int q = 0; q < 4; q++) acc[mi][ni][q] = 0.f;

    const int T = K3 / 64;
    load_tile(0, 0);
    if (T > 1) load_tile(1, 64);

    const int lr16 = lane & 15;        // ldmatrix row-within-16
    const int khv  = (lane >> 4) * 8;  // k half select (0 or 8)

    for (int t = 0; t < T; t++) {
        if (t == T - 1) { CP_WAIT0(); } else { CP_WAIT1(); }
        __syncthreads();

        const uint32_t sA = s0 + (t % 3) * STAGE_B;
        const uint32_t sB = sA + MAT_B;

#pragma unroll
        for (int ks = 0; ks < 64; ks += 16) {
            uint32_t af[4][4], bf[4][2];
#pragma unroll
            for (int mi = 0; mi < 4; mi++) {
                const int row = wm * 64 + mi * 16 + lr16;
                ldm_x4(af[mi], sA + row * SSTR + (ks + khv) * 2);
            }
#pragma unroll
            for (int nh = 0; nh < 2; nh++) {
                uint32_t r[4];
                const int row = wn * 32 + nh * 16 + lr16;
                ldm_x4(r, sB + row * SSTR + (ks + khv) * 2);
                bf[2 * nh + 0][0] = r[0]; bf[2 * nh + 1][0] = r[1];
                bf[2 * nh + 0][1] = r[2]; bf[2 * nh + 1][1] = r[3];
            }
#pragma unroll
            for (int mi = 0; mi < 4; mi++)
#pragma unroll
                for (int ni = 0; ni < 4; ni++)
                    mma16816(acc[mi][ni], af[mi], bf[ni]);
        }

        // prefetch 2 tiles ahead into the buffer consumed 2 iterations ago
        if (t + 2 < T) load_tile((t + 2) % 3, (t + 2) * 64);
    }

    // epilogue
    const int g  = lane >> 2;
    const int tt = lane & 3;
#pragma unroll
    for (int mi = 0; mi < 4; mi++) {
        const int rA = row0 + wm * 64 + mi * 16 + g;
        float* cr0 = C + (size_t)rA * ldc;
        float* cr1 = C + (size_t)(rA + 8) * ldc;
#pragma unroll
        for (int ni = 0; ni < 4; ni++) {
            const int cn = col0 + wn * 32 + ni * 8 + tt * 2;
#pragma unroll
            for (int q = 0; q < 4; q++) {
                const int col = cn + (q & 1);
                if (col >= ncols) continue;
                float v = acc[mi][ni][q];
                if (ACT == 1) {
                    v += bias[col];
                    v = (v > 20.f) ? v : log1pf(expf(v));
                }
                ((q < 2) ? cr0 : cr1)[col] = v;
            }
        }
    }
}

// ---------------- fp32 -> split bf16 converters -------------------------------
__global__ void cvt_act(const float* __restrict__ A, int lda, int K, bf16* __restrict__ A3)
{
    const size_t idx = (size_t)blockIdx.x * blockDim.x + threadIdx.x;
    if (idx >= (size_t)BL * K) return;
    const int m = idx / K, k = idx % K;
    const float v = A[(size_t)m * lda + k];
    const bf16 hi = __float2bfloat16(v);
    const bf16 lo = __float2bfloat16(v - __bfloat162float(hi));
    const size_t base = (size_t)m * 3 * K;
    A3[base + k] = hi; A3[base + K + k] = lo; A3[base + 2 * K + k] = hi;
}

__global__ void cvt_wt(const float* __restrict__ B, int K, int N, int ldb,
                       bf16* __restrict__ B3, int Nrows)
{
    __shared__ float t[32][33];
    const int k0 = blockIdx.y * 32, n0 = blockIdx.x * 32;
    const int tx = threadIdx.x, ty = threadIdx.y;   // 32 x 8
    for (int i = ty; i < 32; i += 8) {
        const int k = k0 + i, n = n0 + tx;
        t[i][tx] = (k < K && n < N) ? B[(size_t)k * ldb + n] : 0.f;
    }
    __syncthreads();
    for (int i = ty; i < 32; i += 8) {
        const int n = n0 + i;
        if (n >= Nrows) continue;
        const int k = k0 + tx;
        const float v = t[tx][i];
        const bf16 hi = __float2bfloat16(v);
        const bf16 lo = __float2bfloat16(v - __bfloat162float(hi));
        const size_t base = (size_t)n * 3 * K;
        B3[base + k] = hi; B3[base + K + k] = hi; B3[base + 2 * K + k] = lo;
    }
}

// ---------------- depthwise causal conv (k=4) + bias + SiLU ------------------
__global__ void conv_silu_kernel(const float* __restrict__ xz,
                                 const float* __restrict__ w,
                                 const float* __restrict__ bias,
                                 float* __restrict__ xs, bf16* __restrict__ xs3)
{
    const int idx = blockIdx.x * blockDim.x + threadIdx.x;
    if (idx >= B_ * L_ * D_INNER) return;
    const int d  = idx & (D_INNER - 1);
    const int bl = idx >> 11;
    const int l  = bl & (L_ - 1);
    const int b  = bl >> 11;

    const float* xbase = xz + (size_t)b * L_ * 4096 + d;
    float acc = bias[d];
    if (l >= 3) acc = fmaf(w[d * 4 + 0], xbase[(size_t)(l - 3) * 4096], acc);
    if (l >= 2) acc = fmaf(w[d * 4 + 1], xbase[(size_t)(l - 2) * 4096], acc);
    if (l >= 1) acc = fmaf(w[d * 4 + 2], xbase[(size_t)(l - 1) * 4096], acc);
    acc = fmaf(w[d * 4 + 3], xbase[(size_t)l * 4096], acc);

    const float s = acc * (1.f / (1.f + __expf(-acc)));
    xs[idx] = s;
    const bf16 hi = __float2bfloat16(s);
    const bf16 lo = __float2bfloat16(s - __bfloat162float(hi));
    const size_t base = (size_t)bl * 6144;
    xs3[base + d] = hi; xs3[base + 2048 + d] = lo; xs3[base + 4096 + d] = hi;
}

// ---------------- selective scan + gating, prefetched 4-step chunks ----------
__global__ __launch_bounds__(256) void scan_kernel(
    const float* __restrict__ delta, const float* __restrict__ dbc,
    const float* __restrict__ xs, const float* __restrict__ xz,
    const float* __restrict__ A_log, const float* __restrict__ Dvec,
    const float* __restrict__ hiddens, bf16* __restrict__ y3)
{
    const int tid = blockIdx.x * blockDim.x + threadIdx.x;
    const int n = tid & 15;
    const int g = tid >> 4;
    const int b = g >> 11;
    const int d = g & (D_INNER - 1);

    const float a = -__expf(A_log[d * D_STATE + n]);
    float h = hiddens[((size_t)b * D_INNER + d) * D_STATE + n];
    const float Dd = Dvec[d];

    const float* dlt  = delta + (size_t)b * L_ * D_INNER + d;
    const float* xp   = xs    + (size_t)b * L_ * D_INNER + d;
    const float* dbcp = dbc   + (size_t)b * L_ * 96;
    const float* resp = xz    + (size_t)b * L_ * 4096 + D_INNER + d;
    bf16* yb = y3 + (size_t)b * L_ * 6144 + d;

    float dtA[4], xvA[4], BvA[4], CvA[4], rvA[4];
    float dtB[4], xvB[4], BvB[4], CvB[4], rvB[4];

    auto loadc = [&](int l0, float* dt, float* xv, float* Bv, float* Cv, float* rv) {
#pragma unroll
        for (int j = 0; j < 4; j++) {
            const int l = l0 + j;
            dt[j] = dlt[(size_t)l * D_INNER];
            xv[j] = xp[(size_t)l * D_INNER];
            Bv[j] = dbcp[l * 96 + DT_RANK + n];
            Cv[j] = dbcp[l * 96 + DT_RANK + D_STATE + n];
            rv[j] = resp[(size_t)l * 4096];
        }
    };
    auto proc = [&](int l0, const float* dt, const float* xv,
                    const float* Bv, const float* Cv, const float* rv) {
#pragma unroll
        for (int j = 0; j < 4; j++) {
            const float dA = __expf(dt[j] * a);
            h = fmaf(dA, h, dt[j] * Bv[j] * xv[j]);
            float s = h * Cv[j];
            s += __shfl_xor_sync(0xffffffffu, s, 1);
            s += __shfl_xor_sync(0xffffffffu, s, 2);
            s += __shfl_xor_sync(0xffffffffu, s, 4);
            s += __shfl_xor_sync(0xffffffffu, s, 8);
            if (n == 0) {
                float y = fmaf(xv[j], Dd, s);
                y *= rv[j] * (1.f / (1.f + __expf(-rv[j])));
                const bf16 hi = __float2bfloat16(y);
                const bf16 lo = __float2bfloat16(y - __bfloat162float(hi));
                bf16* yr = yb + (size_t)(l0 + j) * 6144;
                yr[0] = hi; yr[2048] = lo; yr[4096] = hi;
            }
        }
    };

    loadc(0, dtA, xvA, BvA, CvA, rvA);
    for (int l0 = 0; l0 < L_; l0 += 8) {
        loadc(l0 + 4, dtB, xvB, BvB, CvB, rvB);
        proc(l0, dtA, xvA, BvA, CvA, rvA);
        if (l0 + 8 < L_) loadc(l0 + 8, dtA, xvA, BvA, CvA, rvA);
        proc(l0 + 4, dtB, xvB, BvB, CvB, rvB);
    }
}

// ---------------- launch ------------------------------------------------------
extern "C" void kernel_launch(void* const* d_in, const int* in_sizes, int n_in,
                              void* d_out, int out_size)
{
    const float* u          = (const float*)d_in[0];
    const float* hiddens    = (const float*)d_in[1];
    const float* in_proj_w  = (const float*)d_in[2];
    const float* conv_w     = (const float*)d_in[3];
    const float* conv_b     = (const float*)d_in[4];
    const float* x_proj_w   = (const float*)d_in[5];
    const float* dt_proj_w  = (const float*)d_in[6];
    const float* dt_proj_b  = (const float*)d_in[7];
    const float* A_log      = (const float*)d_in[8];
    const float* Dvec       = (const float*)d_in[9];
    const float* out_proj_w = (const float*)d_in[10];
    float* out = (float*)d_out;

    float *xz, *xs, *dbc, *delta;
    bf16 *u3, *xs3, *dt3, *y3, *w3_in, *w3_xp, *w3_dt, *w3_out;
    cudaGetSymbolAddress((void**)&xz, g_xz);
    cudaGetSymbolAddress((void**)&xs, g_xs);
    cudaGetSymbolAddress((void**)&dbc, g_dbc);
    cudaGetSymbolAddress((void**)&delta, g_delta);
    cudaGetSymbolAddress((void**)&u3, g_u3);
    cudaGetSymbolAddress((void**)&xs3, g_xs3);
    cudaGetSymbolAddress((void**)&dt3, g_dt3);
    cudaGetSymbolAddress((void**)&y3, g_y3);
    cudaGetSymbolAddress((void**)&w3_in, g_w3_in);
    cudaGetSymbolAddress((void**)&w3_xp, g_w3_xp);
    cudaGetSymbolAddress((void**)&w3_dt, g_w3_dt);
    cudaGetSymbolAddress((void**)&w3_out, g_w3_out);

    cudaFuncSetAttribute(gemm_mma<0>, cudaFuncAttributeMaxDynamicSharedMemorySize, GEMM_SMEM);
    cudaFuncSetAttribute(gemm_mma<1>, cudaFuncAttributeMaxDynamicSharedMemorySize, GEMM_SMEM);

    const dim3 tb(32, 8);

    // weight conversions (transposed, split)
    cvt_wt<<<dim3(4096 / 32, 1024 / 32), tb>>>(in_proj_w, 1024, 4096, 4096, w3_in, 4096);
    cvt_wt<<<dim3(128 / 32, 2048 / 32), tb>>>(x_proj_w, 2048, 96, 96, w3_xp, 128);
    cvt_wt<<<dim3(2048 / 32, 64 / 32), tb>>>(dt_proj_w, 64, 2048, 2048, w3_dt, 2048);
    cvt_wt<<<dim3(1024 / 32, 2048 / 32), tb>>>(out_proj_w, 2048, 1024, 1024, w3_out, 1024);

    // u -> split
    cvt_act<<<(int)(((size_t)BL * 1024 + 255) / 256), 256>>>(u, 1024, 1024, u3);

    // 1) in_proj: xz[8192,4096] = u3 @ w3_in^T   (K3 = 3072)
    gemm_mma<0><<<dim3(4096 / 128, BL / 128), 256, GEMM_SMEM>>>(
        u3, w3_in, 3072, xz, 4096, 4096, nullptr);

    // 2) conv + bias + silu -> xs (fp32) + xs3 (split)
    conv_silu_kernel<<<(B_ * L_ * D_INNER + 255) / 256, 256>>>(xz, conv_w, conv_b, xs, xs3);

    // 3) x_proj: dbc[8192,96] = xs3 @ w3_xp^T   (K3 = 6144, N padded to 128)
    gemm_mma<0><<<dim3(1, BL / 128), 256, GEMM_SMEM>>>(
        xs3, w3_xp, 6144, dbc, 96, 96, nullptr);

    // 3b) dbc[:, :64] -> split
    cvt_act<<<(int)(((size_t)BL * 64 + 255) / 256), 256>>>(dbc, 96, 64, dt3);

    // 4) dt_proj + softplus: delta[8192,2048]   (K3 = 192)
    gemm_mma<1><<<dim3(2048 / 128, BL / 128), 256, GEMM_SMEM>>>(
        dt3, w3_dt, 192, delta, 2048, 2048, dt_proj_b);

    // 5) selective scan + D skip + silu(res) gating -> y3 (split)
    scan_kernel<<<(B_ * D_INNER * D_STATE) / 256, 256>>>(
        delta, dbc, xs, xz, A_log, Dvec, hiddens, y3);

    // 6) out_proj: out[8192,1024] = y3 @ w3_out^T   (K3 = 6144)
    gemm_mma<0><<<dim3(1024 / 128, BL / 128), 256, GEMM_SMEM>>>(
        y3, w3_out, 6144, out, 1024, 1024, nullptr);
}

// round 13
// speedup vs baseline: 2.2625x; 1.1420x over previous
#include <cuda_runtime.h>
#include <cuda_bf16.h>
#include <cstdint>

// Problem constants
#define B_ 4
#define L_ 2048
#define D_MODEL 1024
#define D_STATE 16
#define D_INNER 2048
#define D_CONV 4
#define DT_RANK 64
#define BL (B_ * L_)          // 8192 rows

typedef __nv_bfloat16 bf16;

// ---------------- scratch (static device globals; no allocs) ----------------
__device__ float g_xz   [(size_t)BL * 4096];      // in_proj out fp32
__device__ float g_xs   [(size_t)BL * 2048];      // conv+silu fp32 (for scan)
__device__ bf16  g_xs3  [(size_t)BL * 6144];      // conv+silu split bf16 (x_proj A)
__device__ bf16  g_u3   [(size_t)BL * 3072];      // u split bf16 (in_proj A)
__device__ float g_dbc  [(size_t)BL * 96];        // x_proj out fp32
__device__ bf16  g_dt3  [(size_t)BL * 192];       // dbc[:, :64] split bf16 (dt_proj A)
__device__ float g_delta[(size_t)BL * 2048];      // softplus(dt_proj) fp32
__device__ bf16  g_y3   [(size_t)BL * 6144];      // scan out split bf16 (out_proj A)
__device__ bf16  g_w3_in [(size_t)4096 * 3072];   // in_proj_w  -> [N,3K]
__device__ bf16  g_w3_xp [(size_t)128  * 6144];   // x_proj_w   -> [128(pad),3K]
__device__ bf16  g_w3_dt [(size_t)2048 * 192];    // dt_proj_w  -> [N,3K]
__device__ bf16  g_w3_out[(size_t)1024 * 6144];   // out_proj_w -> [N,3K]

// ---------------- helpers -----------------------------------------------------
__device__ __forceinline__ uint32_t smem_u32(const void* p) {
    uint32_t a;
    asm("{ .reg .u64 t; cvta.to.shared.u64 t, %1; cvt.u32.u64 %0, t; }" : "=r"(a) : "l"(p));
    return a;
}
#define CP_ASYNC16(dst, src) \
    asm volatile("cp.async.cg.shared.global [%0], [%1], 16;" :: "r"(dst), "l"(src))
#define CP_COMMIT()  asm volatile("cp.async.commit_group;")
#define CP_WAIT1()   asm volatile("cp.async.wait_group 1;")
#define CP_WAIT0()   asm volatile("cp.async.wait_group 0;")

__device__ __forceinline__ void ldm_x4(uint32_t* r, uint32_t addr) {
    asm volatile("ldmatrix.sync.aligned.m8n8.x4.shared.b16 {%0,%1,%2,%3}, [%4];"
                 : "=r"(r[0]), "=r"(r[1]), "=r"(r[2]), "=r"(r[3]) : "r"(addr));
}
__device__ __forceinline__ void mma16816(float* c, const uint32_t* a, const uint32_t* b) {
    asm volatile(
        "mma.sync.aligned.m16n8k16.row.col.f32.bf16.bf16.f32 "
        "{%0,%1,%2,%3}, {%4,%5,%6,%7}, {%8,%9}, {%0,%1,%2,%3};"
        : "+f"(c[0]), "+f"(c[1]), "+f"(c[2]), "+f"(c[3])
        : "r"(a[0]), "r"(a[1]), "r"(a[2]), "r"(a[3]), "r"(b[0]), "r"(b[1]));
}

#define SSTR   144            // padded row stride bytes (64 bf16 = 128B + 16B pad)

// ---------------- BIG GEMM: 256x128 block, 64x64 warp tile --------------------
// C[M, N] = A3[M, K3] @ B3[N, K3]^T, K-major bf16, fp32 out. No activation.
// 8 warps in 4x2 grid; per ks-step: 8 LDSM -> 32 HMMA. 3-stage cp.async.
// M % 256 == 0, N % 128 == 0, K3 % 64 == 0, T >= 2.
#define BMAT_A (256 * SSTR)       // 36864
#define BMAT_B (128 * SSTR)       // 18432
#define BSTAGE (BMAT_A + BMAT_B)  // 55296
#define BIG_SMEM (3 * BSTAGE)     // 165888

__global__ __launch_bounds__(256, 1)
void gemm_big(const bf16* __restrict__ A3, const bf16* __restrict__ B3, int K3,
              float* __restrict__ C, int ldc)
{
    extern __shared__ __align__(16) char smem[];

    const int tid  = threadIdx.x;
    const int wid  = tid >> 5;
    const int lane = tid & 31;
    const int wm   = wid >> 1;         // 0..3  (64 rows each)
    const int wn   = wid & 1;          // 0..1  (64 cols each)
    const int row0 = blockIdx.y * 256;
    const int col0 = blockIdx.x * 128;

    const uint32_t s0 = smem_u32(smem);

    // cp.async mapping: chunk id -> (row, 16B col). A: 2048 chunks, B: 1024.
    auto load_tile = [&](int stage, int k0) {
        const uint32_t sA = s0 + stage * BSTAGE;
        const uint32_t sB = sA + BMAT_A;
#pragma unroll
        for (int p = 0; p < 8; p++) {
            const int cid = tid + p * 256;
            const int r = cid >> 3, c = cid & 7;
            CP_ASYNC16(sA + r * SSTR + c * 16,
                       A3 + (size_t)(row0 + r) * K3 + k0 + c * 8);
        }
#pragma unroll
        for (int p = 0; p < 4; p++) {
            const int cid = tid + p * 256;
            const int r = cid >> 3, c = cid & 7;
            CP_ASYNC16(sB + r * SSTR + c * 16,
                       B3 + (size_t)(col0 + r) * K3 + k0 + c * 8);
        }
        CP_COMMIT();
    };

    float acc[4][8][4];
#pragma unroll
    for (int mi = 0; mi < 4; mi++)
#pragma unroll
        for (int ni = 0; ni < 8; ni++)
#pragma unroll
            for (int q = 0; q < 4; q++) acc[mi][ni][q] = 0.f;

    const int T = K3 / 64;
    load_tile(0, 0);
    load_tile(1, 64);

    const int lr16 = lane & 15;
    const int khv  = (lane >> 4) * 8;

    for (int t = 0; t < T; t++) {
        if (t == T - 1) { CP_WAIT0(); } else { CP_WAIT1(); }
        __syncthreads();

        const uint32_t sA = s0 + (t % 3) * BSTAGE;
        const uint32_t sB = sA + BMAT_A;

#pragma unroll
        for (int ks = 0; ks < 64; ks += 16) {
            uint32_t af[4][4], bf[8][2];
#pragma unroll
            for (int mi = 0; mi < 4; mi++) {
                const int row = wm * 64 + mi * 16 + lr16;
                ldm_x4(af[mi], sA + row * SSTR + (ks + khv) * 2);
            }
#pragma unroll
            for (int nh = 0; nh < 4; nh++) {
                uint32_t r[4];
                const int row = wn * 64 + nh * 16 + lr16;
                ldm_x4(r, sB + row * SSTR + (ks + khv) * 2);
                bf[2 * nh + 0][0] = r[0]; bf[2 * nh + 1][0] = r[1];
                bf[2 * nh + 0][1] = r[2]; bf[2 * nh + 1][1] = r[3];
            }
#pragma unroll
            for (int mi = 0; mi < 4; mi++)
#pragma unroll
                for (int ni = 0; ni < 8; ni++)
                    mma16816(acc[mi][ni], af[mi], bf[ni]);
        }

        if (t + 2 < T) load_tile((t + 2) % 3, (t + 2) * 64);
    }

    // epilogue
    const int g  = lane >> 2;
    const int tt = lane & 3;
#pragma unroll
    for (int mi = 0; mi < 4; mi++) {
        const int rA = row0 + wm * 64 + mi * 16 + g;
        float* cr0 = C + (size_t)rA * ldc;
        float* cr1 = C + (size_t)(rA + 8) * ldc;
#pragma unroll
        for (int ni = 0; ni < 8; ni++) {
            const int cn = col0 + wn * 64 + ni * 8 + tt * 2;
            cr0[cn]     = acc[mi][ni][0];
            cr0[cn + 1] = acc[mi][ni][1];
            cr1[cn]     = acc[mi][ni][2];
            cr1[cn + 1] = acc[mi][ni][3];
        }
    }
}

// ---------------- 128x128 GEMM (small-N / small-K shapes) ---------------------
// ACT: 0 none, 1 bias+softplus
#define MAT_B  (128 * SSTR)   // 18432
#define STAGE_B (2 * MAT_B)   // 36864
#define GEMM_SMEM (3 * STAGE_B)   // 110592

template<int ACT>
__global__ __launch_bounds__(256, 2)
void gemm_mma(const bf16* __restrict__ A3, const bf16* __restrict__ B3, int K3,
              float* __restrict__ C, int ldc, int ncols,
              const float* __restrict__ bias)
{
    extern __shared__ __align__(16) char smem[];

    const int tid  = threadIdx.x;
    const int wid  = tid >> 5;
    const int lane = tid & 31;
    const int wm   = wid >> 2;         // 0..1
    const int wn   = wid & 3;          // 0..3
    const int row0 = blockIdx.y * 128;
    const int col0 = blockIdx.x * 128;

    const uint32_t s0 = smem_u32(smem);

    const int lr = tid >> 1;
    const int lc = (tid & 1) * 4;
    const bf16* gA = A3 + (size_t)(row0 + lr) * K3 + lc * 8;
    const bf16* gB = B3 + (size_t)(col0 + lr) * K3 + lc * 8;
    const uint32_t sOffA = lr * SSTR + lc * 16;

    auto load_tile = [&](int stage, int k0) {
        const uint32_t sA = s0 + stage * STAGE_B + sOffA;
        const uint32_t sB = sA + MAT_B;
        const bf16* pA = gA + k0;
        const bf16* pB = gB + k0;
#pragma unroll
        for (int c = 0; c < 4; c++) {
            CP_ASYNC16(sA + c * 16, pA + c * 8);
            CP_ASYNC16(sB + c * 16, pB + c * 8);
        }
        CP_COMMIT();
    };

    float acc[4][4][4];
#pragma unroll
    for (int mi = 0; mi < 4; mi++)
#pragma unroll
        for (int ni = 0; ni < 4; ni++)
#pragma unroll
            for (int q = 0; q < 4; q++) acc[mi][ni][q] = 0.f;

    const int T = K3 / 64;
    load_tile(0, 0);
    if (T > 1) load_tile(1, 64);

    const int lr16 = lane & 15;
    const int khv  = (lane >> 4) * 8;

    for (int t = 0; t < T; t++) {
        if (t == T - 1) { CP_WAIT0(); } else { CP_WAIT1(); }
        __syncthreads();

        const uint32_t sA = s0 + (t % 3) * STAGE_B;
        const uint32_t sB = sA + MAT_B;

#pragma unroll
        for (int ks = 0; ks < 64; ks += 16) {
            uint32_t af[4][4], bf[4][2];
#pragma unroll
            for (int mi = 0; mi < 4; mi++) {
                const int row = wm * 64 + mi * 16 + lr16;
                ldm_x4(af[mi], sA + row * SSTR + (ks + khv) * 2);
            }
#pragma unroll
            for (int nh = 0; nh < 2; nh++) {
                uint32_t r[4];
                const int row = wn * 32 + nh * 16 + lr16;
                ldm_x4(r, sB + row * SSTR + (ks + khv) * 2);
                bf[2 * nh + 0][0] = r[0]; bf[2 * nh + 1][0] = r[1];
                bf[2 * nh + 0][1] = r[2]; bf[2 * nh + 1][1] = r[3];
            }
#pragma unroll
            for (int mi = 0; mi < 4; mi++)
#pragma unroll
                for (int ni = 0; ni < 4; ni++)
                    mma16816(acc[mi][ni], af[mi], bf[ni]);
        }

        if (t + 2 < T) load_tile((t + 2) % 3, (t + 2) * 64);
    }

    const int g  = lane >> 2;
    const int tt = lane & 3;
#pragma unroll
    for (int mi = 0; mi < 4; mi++) {
        const int rA = row0 + wm * 64 + mi * 16 + g;
        float* cr0 = C + (size_t)rA * ldc;
        float* cr1 = C + (size_t)(rA + 8) * ldc;
#pragma unroll
        for (int ni = 0; ni < 4; ni++) {
            const int cn = col0 + wn * 32 + ni * 8 + tt * 2;
#pragma unroll
            for (int q = 0; q < 4; q++) {
                const int col = cn + (q & 1);
                if (col >= ncols) continue;
                float v = acc[mi][ni][q];
                if (ACT == 1) {
                    v += bias[col];
                    v = (v > 20.f) ? v : log1pf(expf(v));
                }
                ((q < 2) ? cr0 : cr1)[col] = v;
            }
        }
    }
}

// ---------------- fp32 -> split bf16 converters -------------------------------
__global__ void cvt_act(const float* __restrict__ A, int lda, int K, bf16* __restrict__ A3)
{
    const size_t idx = (size_t)blockIdx.x * blockDim.x + threadIdx.x;
    if (idx >= (size_t)BL * K) return;
    const int m = idx / K, k = idx % K;
    const float v = A[(size_t)m * lda + k];
    const bf16 hi = __float2bfloat16(v);
    const bf16 lo = __float2bfloat16(v - __bfloat162float(hi));
    const size_t base = (size_t)m * 3 * K;
    A3[base + k] = hi; A3[base + K + k] = lo; A3[base + 2 * K + k] = hi;
}

__global__ void cvt_wt(const float* __restrict__ B, int K, int N, int ldb,
                       bf16* __restrict__ B3, int Nrows)
{
    __shared__ float t[32][33];
    const int k0 = blockIdx.y * 32, n0 = blockIdx.x * 32;
    const int tx = threadIdx.x, ty = threadIdx.y;   // 32 x 8
    for (int i = ty; i < 32; i += 8) {
        const int k = k0 + i, n = n0 + tx;
        t[i][tx] = (k < K && n < N) ? B[(size_t)k * ldb + n] : 0.f;
    }
    __syncthreads();
    for (int i = ty; i < 32; i += 8) {
        const int n = n0 + i;
        if (n >= Nrows) continue;
        const int k = k0 + tx;
        const float v = t[tx][i];
        const bf16 hi = __float2bfloat16(v);
        const bf16 lo = __float2bfloat16(v - __bfloat162float(hi));
        const size_t base = (size_t)n * 3 * K;
        B3[base + k] = hi; B3[base + K + k] = hi; B3[base + 2 * K + k] = lo;
    }
}

// ---------------- depthwise causal conv (k=4) + bias + SiLU ------------------
__global__ void conv_silu_kernel(const float* __restrict__ xz,
                                 const float* __restrict__ w,
                                 const float* __restrict__ bias,
                                 float* __restrict__ xs, bf16* __restrict__ xs3)
{
    const int idx = blockIdx.x * blockDim.x + threadIdx.x;
    if (idx >= B_ * L_ * D_INNER) return;
    const int d  = idx & (D_INNER - 1);
    const int bl = idx >> 11;
    const int l  = bl & (L_ - 1);
    const int b  = bl >> 11;

    const float* xbase = xz + (size_t)b * L_ * 4096 + d;
    float acc = bias[d];
    if (l >= 3) acc = fmaf(w[d * 4 + 0], xbase[(size_t)(l - 3) * 4096], acc);
    if (l >= 2) acc = fmaf(w[d * 4 + 1], xbase[(size_t)(l - 2) * 4096], acc);
    if (l >= 1) acc = fmaf(w[d * 4 + 2], xbase[(size_t)(l - 1) * 4096], acc);
    acc = fmaf(w[d * 4 + 3], xbase[(size_t)l * 4096], acc);

    const float s = acc * (1.f / (1.f + __expf(-acc)));
    xs[idx] = s;
    const bf16 hi = __float2bfloat16(s);
    const bf16 lo = __float2bfloat16(s - __bfloat162float(hi));
    const size_t base = (size_t)bl * 6144;
    xs3[base + d] = hi; xs3[base + 2048 + d] = lo; xs3[base + 4096 + d] = hi;
}

// ---------------- selective scan + gating, prefetched 4-step chunks ----------
__global__ __launch_bounds__(256) void scan_kernel(
    const float* __restrict__ delta, const float* __restrict__ dbc,
    const float* __restrict__ xs, const float* __restrict__ xz,
    const float* __restrict__ A_log, const float* __restrict__ Dvec,
    const float* __restrict__ hiddens, bf16* __restrict__ y3)
{
    const int tid = blockIdx.x * blockDim.x + threadIdx.x;
    const int n = tid & 15;
    const int g = tid >> 4;
    const int b = g >> 11;
    const int d = g & (D_INNER - 1);

    const float a = -__expf(A_log[d * D_STATE + n]);
    float h = hiddens[((size_t)b * D_INNER + d) * D_STATE + n];
    const float Dd = Dvec[d];

    const float* dlt  = delta + (size_t)b * L_ * D_INNER + d;
    const float* xp   = xs    + (size_t)b * L_ * D_INNER + d;
    const float* dbcp = dbc   + (size_t)b * L_ * 96;
    const float* resp = xz    + (size_t)b * L_ * 4096 + D_INNER + d;
    bf16* yb = y3 + (size_t)b * L_ * 6144 + d;

    float dtA[4], xvA[4], BvA[4], CvA[4], rvA[4];
    float dtB[4], xvB[4], BvB[4], CvB[4], rvB[4];

    auto loadc = [&](int l0, float* dt, float* xv, float* Bv, float* Cv, float* rv) {
#pragma unroll
        for (int j = 0; j < 4; j++) {
            const int l = l0 + j;
            dt[j] = dlt[(size_t)l * D_INNER];
            xv[j] = xp[(size_t)l * D_INNER];
            Bv[j] = dbcp[l * 96 + DT_RANK + n];
            Cv[j] = dbcp[l * 96 + DT_RANK + D_STATE + n];
            rv[j] = resp[(size_t)l * 4096];
        }
    };
    auto proc = [&](int l0, const float* dt, const float* xv,
                    const float* Bv, const float* Cv, const float* rv) {
#pragma unroll
        for (int j = 0; j < 4; j++) {
            const float dA = __expf(dt[j] * a);
            h = fmaf(dA, h, dt[j] * Bv[j] * xv[j]);
            float s = h * Cv[j];
            s += __shfl_xor_sync(0xffffffffu, s, 1);
            s += __shfl_xor_sync(0xffffffffu, s, 2);
            s += __shfl_xor_sync(0xffffffffu, s, 4);
            s += __shfl_xor_sync(0xffffffffu, s, 8);
            if (n == 0) {
                float y = fmaf(xv[j], Dd, s);
                y *= rv[j] * (1.f / (1.f + __expf(-rv[j])));
                const bf16 hi = __float2bfloat16(y);
                const bf16 lo = __float2bfloat16(y - __bfloat162float(hi));
                bf16* yr = yb + (size_t)(l0 + j) * 6144;
                yr[0] = hi; yr[2048] = lo; yr[4096] = hi;
            }
        }
    };

    loadc(0, dtA, xvA, BvA, CvA, rvA);
    for (int l0 = 0; l0 < L_; l0 += 8) {
        loadc(l0 + 4, dtB, xvB, BvB, CvB, rvB);
        proc(l0, dtA, xvA, BvA, CvA, rvA);
        if (l0 + 8 < L_) loadc(l0 + 8, dtA, xvA, BvA, CvA, rvA);
        proc(l0 + 4, dtB, xvB, BvB, CvB, rvB);
    }
}

// ---------------- launch ------------------------------------------------------
extern "C" void kernel_launch(void* const* d_in, const int* in_sizes, int n_in,
                              void* d_out, int out_size)
{
    const float* u          = (const float*)d_in[0];
    const float* hiddens    = (const float*)d_in[1];
    const float* in_proj_w  = (const float*)d_in[2];
    const float* conv_w     = (const float*)d_in[3];
    const float* conv_b     = (const float*)d_in[4];
    const float* x_proj_w   = (const float*)d_in[5];
    const float* dt_proj_w  = (const float*)d_in[6];
    const float* dt_proj_b  = (const float*)d_in[7];
    const float* A_log      = (const float*)d_in[8];
    const float* Dvec       = (const float*)d_in[9];
    const float* out_proj_w = (const float*)d_in[10];
    float* out = (float*)d_out;

    float *xz, *xs, *dbc, *delta;
    bf16 *u3, *xs3, *dt3, *y3, *w3_in, *w3_xp, *w3_dt, *w3_out;
    cudaGetSymbolAddress((void**)&xz, g_xz);
    cudaGetSymbolAddress((void**)&xs, g_xs);
    cudaGetSymbolAddress((void**)&dbc, g_dbc);
    cudaGetSymbolAddress((void**)&delta, g_delta);
    cudaGetSymbolAddress((void**)&u3, g_u3);
    cudaGetSymbolAddress((void**)&xs3, g_xs3);
    cudaGetSymbolAddress((void**)&dt3, g_dt3);
    cudaGetSymbolAddress((void**)&y3, g_y3);
    cudaGetSymbolAddress((void**)&w3_in, g_w3_in);
    cudaGetSymbolAddress((void**)&w3_xp, g_w3_xp);
    cudaGetSymbolAddress((void**)&w3_dt, g_w3_dt);
    cudaGetSymbolAddress((void**)&w3_out, g_w3_out);

    cudaFuncSetAttribute(gemm_big, cudaFuncAttributeMaxDynamicSharedMemorySize, BIG_SMEM);
    cudaFuncSetAttribute(gemm_mma<0>, cudaFuncAttributeMaxDynamicSharedMemorySize, GEMM_SMEM);
    cudaFuncSetAttribute(gemm_mma<1>, cudaFuncAttributeMaxDynamicSharedMemorySize, GEMM_SMEM);

    const dim3 tb(32, 8);

    // weight conversions (transposed, split)
    cvt_wt<<<dim3(4096 / 32, 1024 / 32), tb>>>(in_proj_w, 1024, 4096, 4096, w3_in, 4096);
    cvt_wt<<<dim3(128 / 32, 2048 / 32), tb>>>(x_proj_w, 2048, 96, 96, w3_xp, 128);
    cvt_wt<<<dim3(2048 / 32, 64 / 32), tb>>>(dt_proj_w, 64, 2048, 2048, w3_dt, 2048);
    cvt_wt<<<dim3(1024 / 32, 2048 / 32), tb>>>(out_proj_w, 2048, 1024, 1024, w3_out, 1024);

    // u -> split
    cvt_act<<<(int)(((size_t)BL * 1024 + 255) / 256), 256>>>(u, 1024, 1024, u3);

    // 1) in_proj: xz[8192,4096] = u3 @ w3_in^T   (K3 = 3072)
    gemm_big<<<dim3(4096 / 128, BL / 256), 256, BIG_SMEM>>>(
        u3, w3_in, 3072, xz, 4096);

    // 2) conv + bias + silu -> xs (fp32) + xs3 (split)
    conv_silu_kernel<<<(B_ * L_ * D_INNER + 255) / 256, 256>>>(xz, conv_w, conv_b, xs, xs3);

    // 3) x_proj: dbc[8192,96] = xs3 @ w3_xp^T   (K3 = 6144, N padded to 128)
    gemm_mma<0><<<dim3(1, BL / 128), 256, GEMM_SMEM>>>(
        xs3, w3_xp, 6144, dbc, 96, 96, nullptr);

    // 3b) dbc[:, :64] -> split
    cvt_act<<<(int)(((size_t)BL * 64 + 255) / 256), 256>>>(dbc, 96, 64, dt3);

    // 4) dt_proj + softplus: delta[8192,2048]   (K3 = 192)
    gemm_mma<1><<<dim3(2048 / 128, BL / 128), 256, GEMM_SMEM>>>(
        dt3, w3_dt, 192, delta, 2048, 2048, dt_proj_b);

    // 5) selective scan + D skip + silu(res) gating -> y3 (split)
    scan_kernel<<<(B_ * D_INNER * D_STATE) / 256, 256>>>(
        delta, dbc, xs, xz, A_log, Dvec, hiddens, y3);

    // 6) out_proj: out[8192,1024] = y3 @ w3_out^T   (K3 = 6144)
    gemm_big<<<dim3(1024 / 128, BL / 256), 256, BIG_SMEM>>>(
        y3, w3_out, 6144, out, 1024);
}

// round 14
// speedup vs baseline: 2.6487x; 1.1707x over previous
#include <cuda_runtime.h>
#include <cuda_bf16.h>
#include <cstdint>

// Problem constants
#define B_ 4
#define L_ 2048
#define D_MODEL 1024
#define D_STATE 16
#define D_INNER 2048
#define D_CONV 4
#define DT_RANK 64
#define BL (B_ * L_)          // 8192 rows

typedef __nv_bfloat16 bf16;

// ---------------- scratch (static device globals; no allocs) ----------------
__device__ float g_xz   [(size_t)BL * 4096];      // in_proj out fp32
__device__ float g_xs   [(size_t)BL * 2048];      // conv+silu fp32 (for scan)
__device__ bf16  g_xs3  [(size_t)BL * 6144];      // conv+silu split bf16 (x_proj A)
__device__ bf16  g_u3   [(size_t)BL * 3072];      // u split bf16 (in_proj A)
__device__ float g_dbc  [(size_t)BL * 96];        // x_proj out fp32
__device__ bf16  g_dt3  [(size_t)BL * 192];       // dbc[:, :64] split bf16 (dt_proj A)
__device__ float g_delta[(size_t)BL * 2048];      // softplus(dt_proj) fp32
__device__ bf16  g_y3   [(size_t)BL * 6144];      // scan out split bf16 (out_proj A)
__device__ bf16  g_w3_in [(size_t)4096 * 3072];   // in_proj_w  -> [N,3K]
__device__ bf16  g_w3_xp [(size_t)128  * 6144];   // x_proj_w   -> [128(pad),3K]
__device__ bf16  g_w3_dt [(size_t)2048 * 192];    // dt_proj_w  -> [N,3K]
__device__ bf16  g_w3_out[(size_t)1024 * 6144];   // out_proj_w -> [N,3K]

// ---------------- helpers -----------------------------------------------------
__device__ __forceinline__ uint32_t smem_u32(const void* p) {
    uint32_t a;
    asm("{ .reg .u64 t; cvta.to.shared.u64 t, %1; cvt.u32.u64 %0, t; }" : "=r"(a) : "l"(p));
    return a;
}
#define CP_ASYNC16(dst, src) \
    asm volatile("cp.async.cg.shared.global [%0], [%1], 16;" :: "r"(dst), "l"(src))
#define CP_COMMIT()  asm volatile("cp.async.commit_group;")
#define CP_WAIT2()   asm volatile("cp.async.wait_group 2;")
#define CP_WAIT1()   asm volatile("cp.async.wait_group 1;")
#define CP_WAIT0()   asm volatile("cp.async.wait_group 0;")

__device__ __forceinline__ void ldm_x4(uint32_t* r, uint32_t addr) {
    asm volatile("ldmatrix.sync.aligned.m8n8.x4.shared.b16 {%0,%1,%2,%3}, [%4];"
                 : "=r"(r[0]), "=r"(r[1]), "=r"(r[2]), "=r"(r[3]) : "r"(addr));
}
__device__ __forceinline__ void mma16816(float* c, const uint32_t* a, const uint32_t* b) {
    asm volatile(
        "mma.sync.aligned.m16n8k16.row.col.f32.bf16.bf16.f32 "
        "{%0,%1,%2,%3}, {%4,%5,%6,%7}, {%8,%9}, {%0,%1,%2,%3};"
        : "+f"(c[0]), "+f"(c[1]), "+f"(c[2]), "+f"(c[3])
        : "r"(a[0]), "r"(a[1]), "r"(a[2]), "r"(a[3]), "r"(b[0]), "r"(b[1]));
}

#define SSTR   144            // padded row stride bytes (64 bf16 = 128B + 16B pad)

// ---------------- BIG GEMM: 256x128 block, 64x64 warp tile, 4-stage ----------
// C[M, N] = A3[M, K3] @ B3[N, K3]^T, K-major bf16, fp32 out. No activation.
// M % 256 == 0, N % 128 == 0, K3 % 64 == 0, T >= 3.
#define BMAT_A (256 * SSTR)       // 36864
#define BMAT_B (128 * SSTR)       // 18432
#define BSTAGE (BMAT_A + BMAT_B)  // 55296
#define BIG_SMEM (4 * BSTAGE)     // 221184

__global__ __launch_bounds__(256, 1)
void gemm_big(const bf16* __restrict__ A3, const bf16* __restrict__ B3, int K3,
              float* __restrict__ C, int ldc)
{
    extern __shared__ __align__(16) char smem[];

    const int tid  = threadIdx.x;
    const int wid  = tid >> 5;
    const int lane = tid & 31;
    const int wm   = wid >> 1;         // 0..3  (64 rows each)
    const int wn   = wid & 1;          // 0..1  (64 cols each)
    const int row0 = blockIdx.y * 256;
    const int col0 = blockIdx.x * 128;

    const uint32_t s0 = smem_u32(smem);

    auto load_tile = [&](int stage, int k0) {
        const uint32_t sA = s0 + stage * BSTAGE;
        const uint32_t sB = sA + BMAT_A;
#pragma unroll
        for (int p = 0; p < 8; p++) {
            const int cid = tid + p * 256;
            const int r = cid >> 3, c = cid & 7;
            CP_ASYNC16(sA + r * SSTR + c * 16,
                       A3 + (size_t)(row0 + r) * K3 + k0 + c * 8);
        }
#pragma unroll
        for (int p = 0; p < 4; p++) {
            const int cid = tid + p * 256;
            const int r = cid >> 3, c = cid & 7;
            CP_ASYNC16(sB + r * SSTR + c * 16,
                       B3 + (size_t)(col0 + r) * K3 + k0 + c * 8);
        }
        CP_COMMIT();
    };

    float acc[4][8][4];
#pragma unroll
    for (int mi = 0; mi < 4; mi++)
#pragma unroll
        for (int ni = 0; ni < 8; ni++)
#pragma unroll
            for (int q = 0; q < 4; q++) acc[mi][ni][q] = 0.f;

    const int T = K3 / 64;
    load_tile(0, 0);
    load_tile(1, 64);
    load_tile(2, 128);

    const int lr16 = lane & 15;
    const int khv  = (lane >> 4) * 8;

    for (int t = 0; t < T; t++) {
        if (t < T - 2)      { CP_WAIT2(); }
        else if (t == T - 2){ CP_WAIT1(); }
        else                { CP_WAIT0(); }
        __syncthreads();

        const uint32_t sA = s0 + (t & 3) * BSTAGE;
        const uint32_t sB = sA + BMAT_A;

#pragma unroll
        for (int ks = 0; ks < 64; ks += 16) {
            uint32_t af[4][4], bf[8][2];
#pragma unroll
            for (int mi = 0; mi < 4; mi++) {
                const int row = wm * 64 + mi * 16 + lr16;
                ldm_x4(af[mi], sA + row * SSTR + (ks + khv) * 2);
            }
#pragma unroll
            for (int nh = 0; nh < 4; nh++) {
                uint32_t r[4];
                const int row = wn * 64 + nh * 16 + lr16;
                ldm_x4(r, sB + row * SSTR + (ks + khv) * 2);
                bf[2 * nh + 0][0] = r[0]; bf[2 * nh + 1][0] = r[1];
                bf[2 * nh + 0][1] = r[2]; bf[2 * nh + 1][1] = r[3];
            }
#pragma unroll
            for (int mi = 0; mi < 4; mi++)
#pragma unroll
                for (int ni = 0; ni < 8; ni++)
                    mma16816(acc[mi][ni], af[mi], bf[ni]);
        }

        if (t + 3 < T) load_tile((t + 3) & 3, (t + 3) * 64);
    }

    // epilogue
    const int g  = lane >> 2;
    const int tt = lane & 3;
#pragma unroll
    for (int mi = 0; mi < 4; mi++) {
        const int rA = row0 + wm * 64 + mi * 16 + g;
        float* cr0 = C + (size_t)rA * ldc;
        float* cr1 = C + (size_t)(rA + 8) * ldc;
#pragma unroll
        for (int ni = 0; ni < 8; ni++) {
            const int cn = col0 + wn * 64 + ni * 8 + tt * 2;
            cr0[cn]     = acc[mi][ni][0];
            cr0[cn + 1] = acc[mi][ni][1];
            cr1[cn]     = acc[mi][ni][2];
            cr1[cn + 1] = acc[mi][ni][3];
        }
    }
}

// ---------------- 128x128 GEMM (small-N / small-K shapes) ---------------------
// ACT: 0 none, 1 bias+softplus
#define MAT_B  (128 * SSTR)   // 18432
#define STAGE_B (2 * MAT_B)   // 36864
#define GEMM_SMEM (3 * STAGE_B)   // 110592

template<int ACT>
__global__ __launch_bounds__(256, 2)
void gemm_mma(const bf16* __restrict__ A3, const bf16* __restrict__ B3, int K3,
              float* __restrict__ C, int ldc, int ncols,
              const float* __restrict__ bias)
{
    extern __shared__ __align__(16) char smem[];

    const int tid  = threadIdx.x;
    const int wid  = tid >> 5;
    const int lane = tid & 31;
    const int wm   = wid >> 2;         // 0..1
    const int wn   = wid & 3;          // 0..3
    const int row0 = blockIdx.y * 128;
    const int col0 = blockIdx.x * 128;

    const uint32_t s0 = smem_u32(smem);

    const int lr = tid >> 1;
    const int lc = (tid & 1) * 4;
    const bf16* gA = A3 + (size_t)(row0 + lr) * K3 + lc * 8;
    const bf16* gB = B3 + (size_t)(col0 + lr) * K3 + lc * 8;
    const uint32_t sOffA = lr * SSTR + lc * 16;

    auto load_tile = [&](int stage, int k0) {
        const uint32_t sA = s0 + stage * STAGE_B + sOffA;
        const uint32_t sB = sA + MAT_B;
        const bf16* pA = gA + k0;
        const bf16* pB = gB + k0;
#pragma unroll
        for (int c = 0; c < 4; c++) {
            CP_ASYNC16(sA + c * 16, pA + c * 8);
            CP_ASYNC16(sB + c * 16, pB + c * 8);
        }
        CP_COMMIT();
    };

    float acc[4][4][4];
#pragma unroll
    for (int mi = 0; mi < 4; mi++)
#pragma unroll
        for (int ni = 0; ni < 4; ni++)
#pragma unroll
            for (int q = 0; q < 4; q++) acc[mi][ni][q] = 0.f;

    const int T = K3 / 64;
    load_tile(0, 0);
    if (T > 1) load_tile(1, 64);

    const int lr16 = lane & 15;
    const int khv  = (lane >> 4) * 8;

    for (int t = 0; t < T; t++) {
        if (t == T - 1) { CP_WAIT0(); } else { CP_WAIT1(); }
        __syncthreads();

        const uint32_t sA = s0 + (t % 3) * STAGE_B;
        const uint32_t sB = sA + MAT_B;

#pragma unroll
        for (int ks = 0; ks < 64; ks += 16) {
            uint32_t af[4][4], bf[4][2];
#pragma unroll
            for (int mi = 0; mi < 4; mi++) {
                const int row = wm * 64 + mi * 16 + lr16;
                ldm_x4(af[mi], sA + row * SSTR + (ks + khv) * 2);
            }
#pragma unroll
            for (int nh = 0; nh < 2; nh++) {
                uint32_t r[4];
                const int row = wn * 32 + nh * 16 + lr16;
                ldm_x4(r, sB + row * SSTR + (ks + khv) * 2);
                bf[2 * nh + 0][0] = r[0]; bf[2 * nh + 1][0] = r[1];
                bf[2 * nh + 0][1] = r[2]; bf[2 * nh + 1][1] = r[3];
            }
#pragma unroll
            for (int mi = 0; mi < 4; mi++)
#pragma unroll
                for (int ni = 0; ni < 4; ni++)
                    mma16816(acc[mi][ni], af[mi], bf[ni]);
        }

        if (t + 2 < T) load_tile((t + 2) % 3, (t + 2) * 64);
    }

    const int g  = lane >> 2;
    const int tt = lane & 3;
#pragma unroll
    for (int mi = 0; mi < 4; mi++) {
        const int rA = row0 + wm * 64 + mi * 16 + g;
        float* cr0 = C + (size_t)rA * ldc;
        float* cr1 = C + (size_t)(rA + 8) * ldc;
#pragma unroll
        for (int ni = 0; ni < 4; ni++) {
            const int cn = col0 + wn * 32 + ni * 8 + tt * 2;
#pragma unroll
            for (int q = 0; q < 4; q++) {
                const int col = cn + (q & 1);
                if (col >= ncols) continue;
                float v = acc[mi][ni][q];
                if (ACT == 1) {
                    v += bias[col];
                    v = (v > 20.f) ? v : log1pf(expf(v));
                }
                ((q < 2) ? cr0 : cr1)[col] = v;
            }
        }
    }
}

// ---------------- fp32 -> split bf16 converters -------------------------------
__global__ void cvt_act(const float* __restrict__ A, int lda, int K, bf16* __restrict__ A3)
{
    const size_t idx = (size_t)blockIdx.x * blockDim.x + threadIdx.x;
    if (idx >= (size_t)BL * K) return;
    const int m = idx / K, k = idx % K;
    const float v = A[(size_t)m * lda + k];
    const bf16 hi = __float2bfloat16(v);
    const bf16 lo = __float2bfloat16(v - __bfloat162float(hi));
    const size_t base = (size_t)m * 3 * K;
    A3[base + k] = hi; A3[base + K + k] = lo; A3[base + 2 * K + k] = hi;
}

__global__ void cvt_wt(const float* __restrict__ B, int K, int N, int ldb,
                       bf16* __restrict__ B3, int Nrows)
{
    __shared__ float t[32][33];
    const int k0 = blockIdx.y * 32, n0 = blockIdx.x * 32;
    const int tx = threadIdx.x, ty = threadIdx.y;   // 32 x 8
    for (int i = ty; i < 32; i += 8) {
        const int k = k0 + i, n = n0 + tx;
        t[i][tx] = (k < K && n < N) ? B[(size_t)k * ldb + n] : 0.f;
    }
    __syncthreads();
    for (int i = ty; i < 32; i += 8) {
        const int n = n0 + i;
        if (n >= Nrows) continue;
        const int k = k0 + tx;
        const float v = t[tx][i];
        const bf16 hi = __float2bfloat16(v);
        const bf16 lo = __float2bfloat16(v - __bfloat162float(hi));
        const size_t base = (size_t)n * 3 * K;
        B3[base + k] = hi; B3[base + K + k] = hi; B3[base + 2 * K + k] = lo;
    }
}

// ---------------- depthwise causal conv (k=4) + bias + SiLU ------------------
__global__ void conv_silu_kernel(const float* __restrict__ xz,
                                 const float* __restrict__ w,
                                 const float* __restrict__ bias,
                                 float* __restrict__ xs, bf16* __restrict__ xs3)
{
    const int idx = blockIdx.x * blockDim.x + threadIdx.x;
    if (idx >= B_ * L_ * D_INNER) return;
    const int d  = idx & (D_INNER - 1);
    const int bl = idx >> 11;
    const int l  = bl & (L_ - 1);
    const int b  = bl >> 11;

    const float* xbase = xz + (size_t)b * L_ * 4096 + d;
    float acc = bias[d];
    if (l >= 3) acc = fmaf(w[d * 4 + 0], xbase[(size_t)(l - 3) * 4096], acc);
    if (l >= 2) acc = fmaf(w[d * 4 + 1], xbase[(size_t)(l - 2) * 4096], acc);
    if (l >= 1) acc = fmaf(w[d * 4 + 2], xbase[(size_t)(l - 1) * 4096], acc);
    acc = fmaf(w[d * 4 + 3], xbase[(size_t)l * 4096], acc);

    const float s = acc * (1.f / (1.f + __expf(-acc)));
    xs[idx] = s;
    const bf16 hi = __float2bfloat16(s);
    const bf16 lo = __float2bfloat16(s - __bfloat162float(hi));
    const size_t base = (size_t)bl * 6144;
    xs3[base + d] = hi; xs3[base + 2048 + d] = lo; xs3[base + 4096 + d] = hi;
}

// ---------------- selective scan + gating, smem-staged chunks of 16 ----------
// Block = 256 threads = 16 channel-groups (16 consecutive d, same b).
// Per 16-step chunk: coalesced stage of delta/xs/res/B/C into smem, compute,
// stage y, coalesced split-bf16 writeout. Fixes the 8x store-sector waste.
__global__ __launch_bounds__(256) void scan_kernel(
    const float* __restrict__ delta, const float* __restrict__ dbc,
    const float* __restrict__ xs, const float* __restrict__ xz,
    const float* __restrict__ A_log, const float* __restrict__ Dvec,
    const float* __restrict__ hiddens, bf16* __restrict__ y3)
{
    __shared__ float sdt[16][16];
    __shared__ float sxv[16][16];
    __shared__ float srv[16][16];
    __shared__ float sy [16][16];
    __shared__ float sBC[16][32];      // cols 0..15 = B, 16..31 = C

    const int tid = threadIdx.x;
    const int n   = tid & 15;          // state index within group
    const int gl  = tid >> 4;          // local group = local d
    const int g   = blockIdx.x * 16 + gl;
    const int b   = g >> 11;
    const int d   = g & (D_INNER - 1);
    const int d0  = d - gl;            // block's first d

    const float a = -__expf(A_log[d * D_STATE + n]);
    float h = hiddens[((size_t)b * D_INNER + d) * D_STATE + n];
    const float Dd = Dvec[d];

    const float* dbcp = dbc + (size_t)b * L_ * 96;

    // staging roles: lr = l-offset (0..15), lc = d-offset (0..15)
    const int lr = tid >> 4, lc = tid & 15;
    const float* dltS = delta + (size_t)b * L_ * 2048 + d0 + lc;
    const float* xsS  = xs    + (size_t)b * L_ * 2048 + d0 + lc;
    const float* rvS  = xz    + (size_t)b * L_ * 4096 + 2048 + d0 + lc;
    bf16* yS = y3 + (size_t)b * L_ * 6144 + d0 + lc;
    // B/C staging: 16 rows x 32 cols; thread t covers (t>>5, t&31) and +8 rows
    const int br = tid >> 5, bc = tid & 31;

    for (int l0 = 0; l0 < L_; l0 += 16) {
        // ---- stage inputs (coalesced) ----
        sdt[lr][lc] = dltS[(size_t)(l0 + lr) * 2048];
        sxv[lr][lc] = xsS [(size_t)(l0 + lr) * 2048];
        srv[lr][lc] = rvS [(size_t)(l0 + lr) * 4096];
        sBC[br    ][bc] = dbcp[(l0 + br    ) * 96 + DT_RANK + bc];
        sBC[br + 8][bc] = dbcp[(l0 + br + 8) * 96 + DT_RANK + bc];
        __syncthreads();

        // ---- 16 sequential steps ----
#pragma unroll
        for (int j = 0; j < 16; j++) {
            const float dt = sdt[j][gl];
            const float xv = sxv[j][gl];
            const float Bv = sBC[j][n];
            const float Cv = sBC[j][16 + n];
            const float dA = __expf(dt * a);
            h = fmaf(dA, h, dt * Bv * xv);
            float s = h * Cv;
            s += __shfl_xor_sync(0xffffffffu, s, 1);
            s += __shfl_xor_sync(0xffffffffu, s, 2);
            s += __shfl_xor_sync(0xffffffffu, s, 4);
            s += __shfl_xor_sync(0xffffffffu, s, 8);
            if (n == 0) {
                float y = fmaf(xv, Dd, s);
                const float rv = srv[j][gl];
                y *= rv * (1.f / (1.f + __expf(-rv)));
                sy[j][gl] = y;
            }
        }
        __syncthreads();

        // ---- coalesced split-bf16 writeout ----
        {
            const float y = sy[lr][lc];
            const bf16 hi = __float2bfloat16(y);
            const bf16 lo = __float2bfloat16(y - __bfloat162float(hi));
            bf16* yr = yS + (size_t)(l0 + lr) * 6144;
            yr[0] = hi; yr[2048] = lo; yr[4096] = hi;
        }
        // next chunk's staging is fenced by the barrier after staging; the
        // only cross-iteration hazard (sy rewrite in j-loop vs this read)
        // is blocked by that same barrier.
    }
}

// ---------------- launch ------------------------------------------------------
extern "C" void kernel_launch(void* const* d_in, const int* in_sizes, int n_in,
                              void* d_out, int out_size)
{
    const float* u          = (const float*)d_in[0];
    const float* hiddens    = (const float*)d_in[1];
    const float* in_proj_w  = (const float*)d_in[2];
    const float* conv_w     = (const float*)d_in[3];
    const float* conv_b     = (const float*)d_in[4];
    const float* x_proj_w   = (const float*)d_in[5];
    const float* dt_proj_w  = (const float*)d_in[6];
    const float* dt_proj_b  = (const float*)d_in[7];
    const float* A_log      = (const float*)d_in[8];
    const float* Dvec       = (const float*)d_in[9];
    const float* out_proj_w = (const float*)d_in[10];
    float* out = (float*)d_out;

    float *xz, *xs, *dbc, *delta;
    bf16 *u3, *xs3, *dt3, *y3, *w3_in, *w3_xp, *w3_dt, *w3_out;
    cudaGetSymbolAddress((void**)&xz, g_xz);
    cudaGetSymbolAddress((void**)&xs, g_xs);
    cudaGetSymbolAddress((void**)&dbc, g_dbc);
    cudaGetSymbolAddress((void**)&delta, g_delta);
    cudaGetSymbolAddress((void**)&u3, g_u3);
    cudaGetSymbolAddress((void**)&xs3, g_xs3);
    cudaGetSymbolAddress((void**)&dt3, g_dt3);
    cudaGetSymbolAddress((void**)&y3, g_y3);
    cudaGetSymbolAddress((void**)&w3_in, g_w3_in);
    cudaGetSymbolAddress((void**)&w3_xp, g_w3_xp);
    cudaGetSymbolAddress((void**)&w3_dt, g_w3_dt);
    cudaGetSymbolAddress((void**)&w3_out, g_w3_out);

    cudaFuncSetAttribute(gemm_big, cudaFuncAttributeMaxDynamicSharedMemorySize, BIG_SMEM);
    cudaFuncSetAttribute(gemm_mma<0>, cudaFuncAttributeMaxDynamicSharedMemorySize, GEMM_SMEM);
    cudaFuncSetAttribute(gemm_mma<1>, cudaFuncAttributeMaxDynamicSharedMemorySize, GEMM_SMEM);

    const dim3 tb(32, 8);

    // weight conversions (transposed, split)
    cvt_wt<<<dim3(4096 / 32, 1024 / 32), tb>>>(in_proj_w, 1024, 4096, 4096, w3_in, 4096);
    cvt_wt<<<dim3(128 / 32, 2048 / 32), tb>>>(x_proj_w, 2048, 96, 96, w3_xp, 128);
    cvt_wt<<<dim3(2048 / 32, 64 / 32), tb>>>(dt_proj_w, 64, 2048, 2048, w3_dt, 2048);
    cvt_wt<<<dim3(1024 / 32, 2048 / 32), tb>>>(out_proj_w, 2048, 1024, 1024, w3_out, 1024);

    // u -> split
    cvt_act<<<(int)(((size_t)BL * 1024 + 255) / 256), 256>>>(u, 1024, 1024, u3);

    // 1) in_proj: xz[8192,4096] = u3 @ w3_in^T   (K3 = 3072)
    gemm_big<<<dim3(4096 / 128, BL / 256), 256, BIG_SMEM>>>(
        u3, w3_in, 3072, xz, 4096);

    // 2) conv + bias + silu -> xs (fp32) + xs3 (split)
    conv_silu_kernel<<<(B_ * L_ * D_INNER + 255) / 256, 256>>>(xz, conv_w, conv_b, xs, xs3);

    // 3) x_proj: dbc[8192,96] = xs3 @ w3_xp^T   (K3 = 6144, N padded to 128)
    gemm_mma<0><<<dim3(1, BL / 128), 256, GEMM_SMEM>>>(
        xs3, w3_xp, 6144, dbc, 96, 96, nullptr);

    // 3b) dbc[:, :64] -> split
    cvt_act<<<(int)(((size_t)BL * 64 + 255) / 256), 256>>>(dbc, 96, 64, dt3);

    // 4) dt_proj + softplus: delta[8192,2048]   (K3 = 192)
    gemm_mma<1><<<dim3(2048 / 128, BL / 128), 256, GEMM_SMEM>>>(
        dt3, w3_dt, 192, delta, 2048, 2048, dt_proj_b);

    // 5) selective scan + D skip + silu(res) gating -> y3 (split)
    scan_kernel<<<(B_ * D_INNER * D_STATE) / 256, 256>>>(
        delta, dbc, xs, xz, A_log, Dvec, hiddens, y3);

    // 6) out_proj: out[8192,1024] = y3 @ w3_out^T   (K3 = 6144)
    gemm_big<<<dim3(1024 / 128, BL / 256), 256, BIG_SMEM>>>(
        y3, w3_out, 6144, out, 1024);
}

// round 15
// speedup vs baseline: 2.7889x; 1.0530x over previous
#include <cuda_runtime.h>
#include <cuda_bf16.h>
#include <cstdint>

// Problem constants
#define B_ 4
#define L_ 2048
#define D_MODEL 1024
#define D_STATE 16
#define D_INNER 2048
#define D_CONV 4
#define DT_RANK 64
#define BL (B_ * L_)          // 8192 rows

typedef __nv_bfloat16 bf16;

// ---------------- scratch (static device globals; no allocs) ----------------
__device__ float g_xz   [(size_t)BL * 4096];      // in_proj out fp32
__device__ float g_xs   [(size_t)BL * 2048];      // conv+silu fp32 (for scan)
__device__ float g_dbc  [(size_t)BL * 96];        // x_proj out fp32
__device__ float g_delta[(size_t)BL * 2048];      // softplus(dt_proj) fp32
// split-bf16 planes (hi / lo), no duplication
__device__ bf16  g_uH [(size_t)BL * 1024],  g_uL [(size_t)BL * 1024];
__device__ bf16  g_xsH[(size_t)BL * 2048],  g_xsL[(size_t)BL * 2048];
__device__ bf16  g_dtH[(size_t)BL * 64],    g_dtL[(size_t)BL * 64];
__device__ bf16  g_yH [(size_t)BL * 2048],  g_yL [(size_t)BL * 2048];
__device__ bf16  g_wiH[(size_t)4096 * 1024], g_wiL[(size_t)4096 * 1024];
__device__ bf16  g_wxH[(size_t)128  * 2048], g_wxL[(size_t)128  * 2048];
__device__ bf16  g_wdH[(size_t)2048 * 64],   g_wdL[(size_t)2048 * 64];
__device__ bf16  g_woH[(size_t)1024 * 2048], g_woL[(size_t)1024 * 2048];

// ---------------- helpers -----------------------------------------------------
__device__ __forceinline__ uint32_t smem_u32(const void* p) {
    uint32_t a;
    asm("{ .reg .u64 t; cvta.to.shared.u64 t, %1; cvt.u32.u64 %0, t; }" : "=r"(a) : "l"(p));
    return a;
}
#define CP_ASYNC16(dst, src) \
    asm volatile("cp.async.cg.shared.global [%0], [%1], 16;" :: "r"(dst), "l"(src))
#define CP_COMMIT()  asm volatile("cp.async.commit_group;")
#define CP_WAIT2()   asm volatile("cp.async.wait_group 2;")
#define CP_WAIT1()   asm volatile("cp.async.wait_group 1;")
#define CP_WAIT0()   asm volatile("cp.async.wait_group 0;")

__device__ __forceinline__ void ldm_x4(uint32_t* r, uint32_t addr) {
    asm volatile("ldmatrix.sync.aligned.m8n8.x4.shared.b16 {%0,%1,%2,%3}, [%4];"
                 : "=r"(r[0]), "=r"(r[1]), "=r"(r[2]), "=r"(r[3]) : "r"(addr));
}
__device__ __forceinline__ void mma16816(float* c, const uint32_t* a, const uint32_t* b) {
    asm volatile(
        "mma.sync.aligned.m16n8k16.row.col.f32.bf16.bf16.f32 "
        "{%0,%1,%2,%3}, {%4,%5,%6,%7}, {%8,%9}, {%0,%1,%2,%3};"
        : "+f"(c[0]), "+f"(c[1]), "+f"(c[2]), "+f"(c[3])
        : "r"(a[0]), "r"(a[1]), "r"(a[2]), "r"(a[3]), "r"(b[0]), "r"(b[1]));
}

#define SSTR   144            // padded row stride bytes (64 bf16 = 128B + 16B pad)

// Plane select for split product  A*B = AhBh + AlBh + AhBl  (segments s=0,1,2)
// A segment: 0:hi 1:lo 2:hi ; B segment: 0:hi 1:hi 2:lo ; offset = k0 mod K.

// ---------------- BIG GEMM: 256x128 block, 64x64 warp tile, 4-stage ----------
#define BMAT_A (256 * SSTR)       // 36864
#define BMAT_B (128 * SSTR)       // 18432
#define BSTAGE (BMAT_A + BMAT_B)  // 55296
#define BIG_SMEM (4 * BSTAGE)     // 221184

__global__ __launch_bounds__(256, 1)
void gemm_big(const bf16* __restrict__ aHi, const bf16* __restrict__ aLo,
              const bf16* __restrict__ bHi, const bf16* __restrict__ bLo,
              int K, float* __restrict__ C, int ldc)
{
    extern __shared__ __align__(16) char smem[];

    const int tid  = threadIdx.x;
    const int wid  = tid >> 5;
    const int lane = tid & 31;
    const int wm   = wid >> 1;         // 0..3
    const int wn   = wid & 1;          // 0..1
    const int row0 = blockIdx.y * 256;
    const int col0 = blockIdx.x * 128;

    const uint32_t s0 = smem_u32(smem);

    auto load_tile = [&](int stage, int k0) {
        const bf16 *pa, *pb; int off;
        if (k0 < K)            { pa = aHi; pb = bHi; off = k0; }
        else if (k0 < 2 * K)   { pa = aLo; pb = bHi; off = k0 - K; }
        else                   { pa = aHi; pb = bLo; off = k0 - 2 * K; }
        const uint32_t sA = s0 + stage * BSTAGE;
        const uint32_t sB = sA + BMAT_A;
#pragma unroll
        for (int p = 0; p < 8; p++) {
            const int cid = tid + p * 256;
            const int r = cid >> 3, c = cid & 7;
            CP_ASYNC16(sA + r * SSTR + c * 16,
                       pa + (size_t)(row0 + r) * K + off + c * 8);
        }
#pragma unroll
        for (int p = 0; p < 4; p++) {
            const int cid = tid + p * 256;
            const int r = cid >> 3, c = cid & 7;
            CP_ASYNC16(sB + r * SSTR + c * 16,
                       pb + (size_t)(col0 + r) * K + off + c * 8);
        }
        CP_COMMIT();
    };

    float acc[4][8][4];
#pragma unroll
    for (int mi = 0; mi < 4; mi++)
#pragma unroll
        for (int ni = 0; ni < 8; ni++)
#pragma unroll
            for (int q = 0; q < 4; q++) acc[mi][ni][q] = 0.f;

    const int T = 3 * K / 64;
    load_tile(0, 0);
    load_tile(1, 64);
    load_tile(2, 128);

    const int lr16 = lane & 15;
    const int khv  = (lane >> 4) * 8;

    for (int t = 0; t < T; t++) {
        if (t < T - 2)      { CP_WAIT2(); }
        else if (t == T - 2){ CP_WAIT1(); }
        else                { CP_WAIT0(); }
        __syncthreads();

        const uint32_t sA = s0 + (t & 3) * BSTAGE;
        const uint32_t sB = sA + BMAT_A;

#pragma unroll
        for (int ks = 0; ks < 64; ks += 16) {
            uint32_t af[4][4], bf[8][2];
#pragma unroll
            for (int mi = 0; mi < 4; mi++) {
                const int row = wm * 64 + mi * 16 + lr16;
                ldm_x4(af[mi], sA + row * SSTR + (ks + khv) * 2);
            }
#pragma unroll
            for (int nh = 0; nh < 4; nh++) {
                uint32_t r[4];
                const int row = wn * 64 + nh * 16 + lr16;
                ldm_x4(r, sB + row * SSTR + (ks + khv) * 2);
                bf[2 * nh + 0][0] = r[0]; bf[2 * nh + 1][0] = r[1];
                bf[2 * nh + 0][1] = r[2]; bf[2 * nh + 1][1] = r[3];
            }
#pragma unroll
            for (int mi = 0; mi < 4; mi++)
#pragma unroll
                for (int ni = 0; ni < 8; ni++)
                    mma16816(acc[mi][ni], af[mi], bf[ni]);
        }

        if (t + 3 < T) load_tile((t + 3) & 3, (t + 3) * 64);
    }

    const int g  = lane >> 2;
    const int tt = lane & 3;
#pragma unroll
    for (int mi = 0; mi < 4; mi++) {
        const int rA = row0 + wm * 64 + mi * 16 + g;
        float* cr0 = C + (size_t)rA * ldc;
        float* cr1 = C + (size_t)(rA + 8) * ldc;
#pragma unroll
        for (int ni = 0; ni < 8; ni++) {
            const int cn = col0 + wn * 64 + ni * 8 + tt * 2;
            cr0[cn]     = acc[mi][ni][0];
            cr0[cn + 1] = acc[mi][ni][1];
            cr1[cn]     = acc[mi][ni][2];
            cr1[cn + 1] = acc[mi][ni][3];
        }
    }
}

// ---------------- 128x128 GEMM (dt_proj: K=64, bias+softplus) -----------------
#define MAT_B  (128 * SSTR)   // 18432
#define STAGE_B (2 * MAT_B)   // 36864
#define GEMM_SMEM (3 * STAGE_B)   // 110592

__global__ __launch_bounds__(256, 2)
void gemm_mma(const bf16* __restrict__ aHi, const bf16* __restrict__ aLo,
              const bf16* __restrict__ bHi, const bf16* __restrict__ bLo,
              int K, float* __restrict__ C, int ldc,
              const float* __restrict__ bias)
{
    extern __shared__ __align__(16) char smem[];

    const int tid  = threadIdx.x;
    const int wid  = tid >> 5;
    const int lane = tid & 31;
    const int wm   = wid >> 2;         // 0..1
    const int wn   = wid & 3;          // 0..3
    const int row0 = blockIdx.y * 128;
    const int col0 = blockIdx.x * 128;

    const uint32_t s0 = smem_u32(smem);

    auto load_tile = [&](int stage, int k0) {
        const bf16 *pa, *pb; int off;
        if (k0 < K)            { pa = aHi; pb = bHi; off = k0; }
        else if (k0 < 2 * K)   { pa = aLo; pb = bHi; off = k0 - K; }
        else                   { pa = aHi; pb = bLo; off = k0 - 2 * K; }
        const uint32_t sA = s0 + stage * STAGE_B;
        const uint32_t sB = sA + MAT_B;
#pragma unroll
        for (int p = 0; p < 4; p++) {
            const int cid = tid + p * 256;
            const int r = cid >> 3, c = cid & 7;
            CP_ASYNC16(sA + r * SSTR + c * 16,
                       pa + (size_t)(row0 + r) * K + off + c * 8);
            CP_ASYNC16(sB + r * SSTR + c * 16,
                       pb + (size_t)(col0 + r) * K + off + c * 8);
        }
        CP_COMMIT();
    };

    float acc[4][4][4];
#pragma unroll
    for (int mi = 0; mi < 4; mi++)
#pragma unroll
        for (int ni = 0; ni < 4; ni++)
#pragma unroll
            for (int q = 0; q < 4; q++) acc[mi][ni][q] = 0.f;

    const int T = 3 * K / 64;
    load_tile(0, 0);
    if (T > 1) load_tile(1, 64);

    const int lr16 = lane & 15;
    const int khv  = (lane >> 4) * 8;

    for (int t = 0; t < T; t++) {
        if (t == T - 1) { CP_WAIT0(); } else { CP_WAIT1(); }
        __syncthreads();

        const uint32_t sA = s0 + (t % 3) * STAGE_B;
        const uint32_t sB = sA + MAT_B;

#pragma unroll
        for (int ks = 0; ks < 64; ks += 16) {
            uint32_t af[4][4], bf[4][2];
#pragma unroll
            for (int mi = 0; mi < 4; mi++) {
                const int row = wm * 64 + mi * 16 + lr16;
                ldm_x4(af[mi], sA + row * SSTR + (ks + khv) * 2);
            }
#pragma unroll
            for (int nh = 0; nh < 2; nh++) {
                uint32_t r[4];
                const int row = wn * 32 + nh * 16 + lr16;
                ldm_x4(r, sB + row * SSTR + (ks + khv) * 2);
                bf[2 * nh + 0][0] = r[0]; bf[2 * nh + 1][0] = r[1];
                bf[2 * nh + 0][1] = r[2]; bf[2 * nh + 1][1] = r[3];
            }
#pragma unroll
            for (int mi = 0; mi < 4; mi++)
#pragma unroll
                for (int ni = 0; ni < 4; ni++)
                    mma16816(acc[mi][ni], af[mi], bf[ni]);
        }

        if (t + 2 < T) load_tile((t + 2) % 3, (t + 2) * 64);
    }

    const int g  = lane >> 2;
    const int tt = lane & 3;
#pragma unroll
    for (int mi = 0; mi < 4; mi++) {
        const int rA = row0 + wm * 64 + mi * 16 + g;
        float* cr0 = C + (size_t)rA * ldc;
        float* cr1 = C + (size_t)(rA + 8) * ldc;
#pragma unroll
        for (int ni = 0; ni < 4; ni++) {
            const int cn = col0 + wn * 32 + ni * 8 + tt * 2;
#pragma unroll
            for (int q = 0; q < 4; q++) {
                const int col = cn + (q & 1);
                float v = acc[mi][ni][q];
                v += bias[col];
                v = (v > 20.f) ? v : log1pf(expf(v));
                ((q < 2) ? cr0 : cr1)[col] = v;
            }
        }
    }
}

// ---------------- 64x128 GEMM (x_proj: full-chip occupancy) -------------------
#define M64_A  (64 * SSTR)         // 9216
#define M64_B  (128 * SSTR)        // 18432
#define M64_ST (M64_A + M64_B)     // 27648
#define G64_SMEM (3 * M64_ST)      // 82944

__global__ __launch_bounds__(256, 2)
void gemm_m64(const bf16* __restrict__ aHi, const bf16* __restrict__ aLo,
              const bf16* __restrict__ bHi, const bf16* __restrict__ bLo,
              int K, float* __restrict__ C, int ldc, int ncols)
{
    extern __shared__ __align__(16) char smem[];

    const int tid  = threadIdx.x;
    const int wid  = tid >> 5;
    const int lane = tid & 31;
    const int wm   = wid >> 2;         // 0..1  (32 rows each)
    const int wn   = wid & 3;          // 0..3  (32 cols each)
    const int row0 = blockIdx.y * 64;
    const int col0 = 0;

    const uint32_t s0 = smem_u32(smem);

    auto load_tile = [&](int stage, int k0) {
        const bf16 *pa, *pb; int off;
        if (k0 < K)            { pa = aHi; pb = bHi; off = k0; }
        else if (k0 < 2 * K)   { pa = aLo; pb = bHi; off = k0 - K; }
        else                   { pa = aHi; pb = bLo; off = k0 - 2 * K; }
        const uint32_t sA = s0 + stage * M64_ST;
        const uint32_t sB = sA + M64_A;
#pragma unroll
        for (int p = 0; p < 2; p++) {
            const int cid = tid + p * 256;
            const int r = cid >> 3, c = cid & 7;
            CP_ASYNC16(sA + r * SSTR + c * 16,
                       pa + (size_t)(row0 + r) * K + off + c * 8);
        }
#pragma unroll
        for (int p = 0; p < 4; p++) {
            const int cid = tid + p * 256;
            const int r = cid >> 3, c = cid & 7;
            CP_ASYNC16(sB + r * SSTR + c * 16,
                       pb + (size_t)(col0 + r) * K + off + c * 8);
        }
        CP_COMMIT();
    };

    float acc[2][4][4];
#pragma unroll
    for (int mi = 0; mi < 2; mi++)
#pragma unroll
        for (int ni = 0; ni < 4; ni++)
#pragma unroll
            for (int q = 0; q < 4; q++) acc[mi][ni][q] = 0.f;

    const int T = 3 * K / 64;
    load_tile(0, 0);
    load_tile(1, 64);

    const int lr16 = lane & 15;
    const int khv  = (lane >> 4) * 8;

    for (int t = 0; t < T; t++) {
        if (t == T - 1) { CP_WAIT0(); } else { CP_WAIT1(); }
        __syncthreads();

        const uint32_t sA = s0 + (t % 3) * M64_ST;
        const uint32_t sB = sA + M64_A;

#pragma unroll
        for (int ks = 0; ks < 64; ks += 16) {
            uint32_t af[2][4], bf[4][2];
#pragma unroll
            for (int mi = 0; mi < 2; mi++) {
                const int row = wm * 32 + mi * 16 + lr16;
                ldm_x4(af[mi], sA + row * SSTR + (ks + khv) * 2);
            }
#pragma unroll
            for (int nh = 0; nh < 2; nh++) {
                uint32_t r[4];
                const int row = wn * 32 + nh * 16 + lr16;
                ldm_x4(r, sB + row * SSTR + (ks + khv) * 2);
                bf[2 * nh + 0][0] = r[0]; bf[2 * nh + 1][0] = r[1];
                bf[2 * nh + 0][1] = r[2]; bf[2 * nh + 1][1] = r[3];
            }
#pragma unroll
            for (int mi = 0; mi < 2; mi++)
#pragma unroll
                for (int ni = 0; ni < 4; ni++)
                    mma16816(acc[mi][ni], af[mi], bf[ni]);
        }

        if (t + 2 < T) load_tile((t + 2) % 3, (t + 2) * 64);
    }

    const int g  = lane >> 2;
    const int tt = lane & 3;
#pragma unroll
    for (int mi = 0; mi < 2; mi++) {
        const int rA = row0 + wm * 32 + mi * 16 + g;
        float* cr0 = C + (size_t)rA * ldc;
        float* cr1 = C + (size_t)(rA + 8) * ldc;
#pragma unroll
        for (int ni = 0; ni < 4; ni++) {
            const int cn = col0 + wn * 32 + ni * 8 + tt * 2;
#pragma unroll
            for (int q = 0; q < 4; q++) {
                const int col = cn + (q & 1);
                if (col >= ncols) continue;
                ((q < 2) ? cr0 : cr1)[col] = acc[mi][ni][q];
            }
        }
    }
}

// ---------------- fp32 -> split bf16 converters (planes) ----------------------
__global__ void cvt_act(const float* __restrict__ A, int lda, int K,
                        bf16* __restrict__ aH, bf16* __restrict__ aL)
{
    const size_t idx = (size_t)blockIdx.x * blockDim.x + threadIdx.x;
    if (idx >= (size_t)BL * K) return;
    const int m = idx / K, k = idx % K;
    const float v = A[(size_t)m * lda + k];
    const bf16 hi = __float2bfloat16(v);
    const bf16 lo = __float2bfloat16(v - __bfloat162float(hi));
    aH[idx] = hi; aL[idx] = lo;
}

__global__ void cvt_wt(const float* __restrict__ B, int K, int N, int ldb,
                       bf16* __restrict__ wH, bf16* __restrict__ wL, int Nrows)
{
    __shared__ float t[32][33];
    const int k0 = blockIdx.y * 32, n0 = blockIdx.x * 32;
    const int tx = threadIdx.x, ty = threadIdx.y;   // 32 x 8
    for (int i = ty; i < 32; i += 8) {
        const int k = k0 + i, n = n0 + tx;
        t[i][tx] = (k < K && n < N) ? B[(size_t)k * ldb + n] : 0.f;
    }
    __syncthreads();
    for (int i = ty; i < 32; i += 8) {
        const int n = n0 + i;
        if (n >= Nrows) continue;
        const int k = k0 + tx;
        const float v = t[tx][i];
        const bf16 hi = __float2bfloat16(v);
        const bf16 lo = __float2bfloat16(v - __bfloat162float(hi));
        const size_t o = (size_t)n * K + k;
        wH[o] = hi; wL[o] = lo;
    }
}

// ---------------- depthwise causal conv (k=4) + bias + SiLU ------------------
__global__ void conv_silu_kernel(const float* __restrict__ xz,
                                 const float* __restrict__ w,
                                 const float* __restrict__ bias,
                                 float* __restrict__ xs,
                                 bf16* __restrict__ xsH, bf16* __restrict__ xsL)
{
    const int idx = blockIdx.x * blockDim.x + threadIdx.x;
    if (idx >= B_ * L_ * D_INNER) return;
    const int d  = idx & (D_INNER - 1);
    const int bl = idx >> 11;
    const int l  = bl & (L_ - 1);
    const int b  = bl >> 11;

    const float* xbase = xz + (size_t)b * L_ * 4096 + d;
    float acc = bias[d];
    if (l >= 3) acc = fmaf(w[d * 4 + 0], xbase[(size_t)(l - 3) * 4096], acc);
    if (l >= 2) acc = fmaf(w[d * 4 + 1], xbase[(size_t)(l - 2) * 4096], acc);
    if (l >= 1) acc = fmaf(w[d * 4 + 2], xbase[(size_t)(l - 1) * 4096], acc);
    acc = fmaf(w[d * 4 + 3], xbase[(size_t)l * 4096], acc);

    const float s = acc * (1.f / (1.f + __expf(-acc)));
    xs[idx] = s;
    const bf16 hi = __float2bfloat16(s);
    const bf16 lo = __float2bfloat16(s - __bfloat162float(hi));
    xsH[idx] = hi; xsL[idx] = lo;
}

// ---------------- selective scan + gating, smem-staged chunks of 16 ----------
__global__ __launch_bounds__(256) void scan_kernel(
    const float* __restrict__ delta, const float* __restrict__ dbc,
    const float* __restrict__ xs, const float* __restrict__ xz,
    const float* __restrict__ A_log, const float* __restrict__ Dvec,
    const float* __restrict__ hiddens,
    bf16* __restrict__ yH, bf16* __restrict__ yL)
{
    __shared__ float sdt[16][16];
    __shared__ float sxv[16][16];
    __shared__ float srv[16][16];
    __shared__ float sy [16][16];
    __shared__ float sBC[16][32];

    const int tid = threadIdx.x;
    const int n   = tid & 15;
    const int gl  = tid >> 4;
    const int g   = blockIdx.x * 16 + gl;
    const int b   = g >> 11;
    const int d   = g & (D_INNER - 1);
    const int d0  = d - gl;

    const float a = -__expf(A_log[d * D_STATE + n]);
    float h = hiddens[((size_t)b * D_INNER + d) * D_STATE + n];
    const float Dd = Dvec[d];

    const float* dbcp = dbc + (size_t)b * L_ * 96;

    const int lr = tid >> 4, lc = tid & 15;
    const float* dltS = delta + (size_t)b * L_ * 2048 + d0 + lc;
    const float* xsS  = xs    + (size_t)b * L_ * 2048 + d0 + lc;
    const float* rvS  = xz    + (size_t)b * L_ * 4096 + 2048 + d0 + lc;
    bf16* yHS = yH + (size_t)b * L_ * 2048 + d0 + lc;
    bf16* yLS = yL + (size_t)b * L_ * 2048 + d0 + lc;
    const int br = tid >> 5, bc = tid & 31;

    for (int l0 = 0; l0 < L_; l0 += 16) {
        sdt[lr][lc] = dltS[(size_t)(l0 + lr) * 2048];
        sxv[lr][lc] = xsS [(size_t)(l0 + lr) * 2048];
        srv[lr][lc] = rvS [(size_t)(l0 + lr) * 4096];
        sBC[br    ][bc] = dbcp[(l0 + br    ) * 96 + DT_RANK + bc];
        sBC[br + 8][bc] = dbcp[(l0 + br + 8) * 96 + DT_RANK + bc];
        __syncthreads();

#pragma unroll
        for (int j = 0; j < 16; j++) {
            const float dt = sdt[j][gl];
            const float xv = sxv[j][gl];
            const float Bv = sBC[j][n];
            const float Cv = sBC[j][16 + n];
            const float dA = __expf(dt * a);
            h = fmaf(dA, h, dt * Bv * xv);
            float s = h * Cv;
            s += __shfl_xor_sync(0xffffffffu, s, 1);
            s += __shfl_xor_sync(0xffffffffu, s, 2);
            s += __shfl_xor_sync(0xffffffffu, s, 4);
            s += __shfl_xor_sync(0xffffffffu, s, 8);
            if (n == 0) {
                float y = fmaf(xv, Dd, s);
                const float rv = srv[j][gl];
                y *= rv * (1.f / (1.f + __expf(-rv)));
                sy[j][gl] = y;
            }
        }
        __syncthreads();

        {
            const float y = sy[lr][lc];
            const bf16 hi = __float2bfloat16(y);
            const bf16 lo = __float2bfloat16(y - __bfloat162float(hi));
            yHS[(size_t)(l0 + lr) * 2048] = hi;
            yLS[(size_t)(l0 + lr) * 2048] = lo;
        }
    }
}

// ---------------- launch ------------------------------------------------------
extern "C" void kernel_launch(void* const* d_in, const int* in_sizes, int n_in,
                              void* d_out, int out_size)
{
    const float* u          = (const float*)d_in[0];
    const float* hiddens    = (const float*)d_in[1];
    const float* in_proj_w  = (const float*)d_in[2];
    const float* conv_w     = (const float*)d_in[3];
    const float* conv_b     = (const float*)d_in[4];
    const float* x_proj_w   = (const float*)d_in[5];
    const float* dt_proj_w  = (const float*)d_in[6];
    const float* dt_proj_b  = (const float*)d_in[7];
    const float* A_log      = (const float*)d_in[8];
    const float* Dvec       = (const float*)d_in[9];
    const float* out_proj_w = (const float*)d_in[10];
    float* out = (float*)d_out;

    float *xz, *xs, *dbc, *delta;
    bf16 *uH, *uL, *xsH, *xsL, *dtH, *dtL, *yH, *yL;
    bf16 *wiH, *wiL, *wxH, *wxL, *wdH, *wdL, *woH, *woL;
    cudaGetSymbolAddress((void**)&xz, g_xz);
    cudaGetSymbolAddress((void**)&xs, g_xs);
    cudaGetSymbolAddress((void**)&dbc, g_dbc);
    cudaGetSymbolAddress((void**)&delta, g_delta);
    cudaGetSymbolAddress((void**)&uH, g_uH);   cudaGetSymbolAddress((void**)&uL, g_uL);
    cudaGetSymbolAddress((void**)&xsH, g_xsH); cudaGetSymbolAddress((void**)&xsL, g_xsL);
    cudaGetSymbolAddress((void**)&dtH, g_dtH); cudaGetSymbolAddress((void**)&dtL, g_dtL);
    cudaGetSymbolAddress((void**)&yH, g_yH);   cudaGetSymbolAddress((void**)&yL, g_yL);
    cudaGetSymbolAddress((void**)&wiH, g_wiH); cudaGetSymbolAddress((void**)&wiL, g_wiL);
    cudaGetSymbolAddress((void**)&wxH, g_wxH); cudaGetSymbolAddress((void**)&wxL, g_wxL);
    cudaGetSymbolAddress((void**)&wdH, g_wdH); cudaGetSymbolAddress((void**)&wdL, g_wdL);
    cudaGetSymbolAddress((void**)&woH, g_woH); cudaGetSymbolAddress((void**)&woL, g_woL);

    cudaFuncSetAttribute(gemm_big, cudaFuncAttributeMaxDynamicSharedMemorySize, BIG_SMEM);
    cudaFuncSetAttribute(gemm_mma, cudaFuncAttributeMaxDynamicSharedMemorySize, GEMM_SMEM);
    cudaFuncSetAttribute(gemm_m64, cudaFuncAttributeMaxDynamicSharedMemorySize, G64_SMEM);

    const dim3 tb(32, 8);

    // weight conversions (transposed, hi/lo planes)
    cvt_wt<<<dim3(4096 / 32, 1024 / 32), tb>>>(in_proj_w, 1024, 4096, 4096, wiH, wiL, 4096);
    cvt_wt<<<dim3(128 / 32, 2048 / 32), tb>>>(x_proj_w, 2048, 96, 96, wxH, wxL, 128);
    cvt_wt<<<dim3(2048 / 32, 64 / 32), tb>>>(dt_proj_w, 64, 2048, 2048, wdH, wdL, 2048);
    cvt_wt<<<dim3(1024 / 32, 2048 / 32), tb>>>(out_proj_w, 2048, 1024, 1024, woH, woL, 1024);

    // u -> planes
    cvt_act<<<(int)(((size_t)BL * 1024 + 255) / 256), 256>>>(u, 1024, 1024, uH, uL);

    // 1) in_proj: xz[8192,4096], K=1024 (T=48)
    gemm_big<<<dim3(4096 / 128, BL / 256), 256, BIG_SMEM>>>(
        uH, uL, wiH, wiL, 1024, xz, 4096);

    // 2) conv + bias + silu -> xs (fp32) + xsH/xsL
    conv_silu_kernel<<<(B_ * L_ * D_INNER + 255) / 256, 256>>>(
        xz, conv_w, conv_b, xs, xsH, xsL);

    // 3) x_proj: dbc[8192,96], K=2048 (T=96), 128 CTAs
    gemm_m64<<<dim3(1, BL / 64), 256, G64_SMEM>>>(
        xsH, xsL, wxH, wxL, 2048, dbc, 96, 96);

    // 3b) dbc[:, :64] -> planes
    cvt_act<<<(int)(((size_t)BL * 64 + 255) / 256), 256>>>(dbc, 96, 64, dtH, dtL);

    // 4) dt_proj + softplus: delta[8192,2048], K=64 (T=3)
    gemm_mma<<<dim3(2048 / 128, BL / 128), 256, GEMM_SMEM>>>(
        dtH, dtL, wdH, wdL, 64, delta, 2048, dt_proj_b);

    // 5) selective scan + D skip + silu(res) gating -> yH/yL
    scan_kernel<<<(B_ * D_INNER * D_STATE) / 256, 256>>>(
        delta, dbc, xs, xz, A_log, Dvec, hiddens, yH, yL);

    // 6) out_proj: out[8192,1024], K=2048 (T=96)
    gemm_big<<<dim3(1024 / 128, BL / 256), 256, BIG_SMEM>>>(
        yH, yL, woH, woL, 2048, out, 1024);
}

// round 16
// speedup vs baseline: 2.7910x; 1.0007x over previous
#include <cuda_runtime.h>
#include <cuda_bf16.h>
#include <cstdint>

// Problem constants
#define B_ 4
#define L_ 2048
#define D_MODEL 1024
#define D_STATE 16
#define D_INNER 2048
#define D_CONV 4
#define DT_RANK 64
#define BL (B_ * L_)          // 8192 rows

typedef __nv_bfloat16 bf16;

// ---------------- scratch (static device globals; no allocs) ----------------
__device__ float g_xz   [(size_t)BL * 4096];      // in_proj out fp32
__device__ float g_xs   [(size_t)BL * 2048];      // conv+silu fp32 (for scan)
__device__ float g_bc   [(size_t)BL * 32];        // x_proj B/C cols (fp32)
__device__ float g_delta[(size_t)BL * 2048];      // softplus(dt_proj) fp32
// split-bf16 planes (hi / lo)
__device__ bf16  g_uH [(size_t)BL * 1024],  g_uL [(size_t)BL * 1024];
__device__ bf16  g_xsH[(size_t)BL * 2048],  g_xsL[(size_t)BL * 2048];
__device__ bf16  g_dtH[(size_t)BL * 64],    g_dtL[(size_t)BL * 64];
__device__ bf16  g_yH [(size_t)BL * 2048],  g_yL [(size_t)BL * 2048];
__device__ bf16  g_wiH[(size_t)4096 * 1024], g_wiL[(size_t)4096 * 1024];
__device__ bf16  g_wxH[(size_t)128  * 2048], g_wxL[(size_t)128  * 2048];
__device__ bf16  g_wdH[(size_t)2048 * 64],   g_wdL[(size_t)2048 * 64];
__device__ bf16  g_woH[(size_t)1024 * 2048], g_woL[(size_t)1024 * 2048];

// ---------------- helpers -----------------------------------------------------
__device__ __forceinline__ uint32_t smem_u32(const void* p) {
    uint32_t a;
    asm("{ .reg .u64 t; cvta.to.shared.u64 t, %1; cvt.u32.u64 %0, t; }" : "=r"(a) : "l"(p));
    return a;
}
#define CP_ASYNC16(dst, src) \
    asm volatile("cp.async.cg.shared.global [%0], [%1], 16;" :: "r"(dst), "l"(src))
#define CP_COMMIT()  asm volatile("cp.async.commit_group;")
#define CP_WAIT2()   asm volatile("cp.async.wait_group 2;")
#define CP_WAIT1()   asm volatile("cp.async.wait_group 1;")
#define CP_WAIT0()   asm volatile("cp.async.wait_group 0;")

__device__ __forceinline__ void ldm_x4(uint32_t* r, uint32_t addr) {
    asm volatile("ldmatrix.sync.aligned.m8n8.x4.shared.b16 {%0,%1,%2,%3}, [%4];"
                 : "=r"(r[0]), "=r"(r[1]), "=r"(r[2]), "=r"(r[3]) : "r"(addr));
}
__device__ __forceinline__ void mma16816(float* c, const uint32_t* a, const uint32_t* b) {
    asm volatile(
        "mma.sync.aligned.m16n8k16.row.col.f32.bf16.bf16.f32 "
        "{%0,%1,%2,%3}, {%4,%5,%6,%7}, {%8,%9}, {%0,%1,%2,%3};"
        : "+f"(c[0]), "+f"(c[1]), "+f"(c[2]), "+f"(c[3])
        : "r"(a[0]), "r"(a[1]), "r"(a[2]), "r"(a[3]), "r"(b[0]), "r"(b[1]));
}

#define SSTR   144            // padded row stride bytes (64 bf16 = 128B + 16B pad)

// Plane select for split product  A*B = AhBh + AlBh + AhBl  (segments s=0,1,2)

// ---------------- BIG GEMM: 256x128 block, 64x64 warp tile, 4-stage ----------
#define BMAT_A (256 * SSTR)       // 36864
#define BMAT_B (128 * SSTR)       // 18432
#define BSTAGE (BMAT_A + BMAT_B)  // 55296
#define BIG_SMEM (4 * BSTAGE)     // 221184

__global__ __launch_bounds__(256, 1)
void gemm_big(const bf16* __restrict__ aHi, const bf16* __restrict__ aLo,
              const bf16* __restrict__ bHi, const bf16* __restrict__ bLo,
              int K, float* __restrict__ C, int ldc)
{
    extern __shared__ __align__(16) char smem[];

    const int tid  = threadIdx.x;
    const int wid  = tid >> 5;
    const int lane = tid & 31;
    const int wm   = wid >> 1;         // 0..3
    const int wn   = wid & 1;          // 0..1
    const int row0 = blockIdx.y * 256;
    const int col0 = blockIdx.x * 128;

    const uint32_t s0 = smem_u32(smem);

    auto load_tile = [&](int stage, int k0) {
        const bf16 *pa, *pb; int off;
        if (k0 < K)            { pa = aHi; pb = bHi; off = k0; }
        else if (k0 < 2 * K)   { pa = aLo; pb = bHi; off = k0 - K; }
        else                   { pa = aHi; pb = bLo; off = k0 - 2 * K; }
        const uint32_t sA = s0 + stage * BSTAGE;
        const uint32_t sB = sA + BMAT_A;
#pragma unroll
        for (int p = 0; p < 8; p++) {
            const int cid = tid + p * 256;
            const int r = cid >> 3, c = cid & 7;
            CP_ASYNC16(sA + r * SSTR + c * 16,
                       pa + (size_t)(row0 + r) * K + off + c * 8);
        }
#pragma unroll
        for (int p = 0; p < 4; p++) {
            const int cid = tid + p * 256;
            const int r = cid >> 3, c = cid & 7;
            CP_ASYNC16(sB + r * SSTR + c * 16,
                       pb + (size_t)(col0 + r) * K + off + c * 8);
        }
        CP_COMMIT();
    };

    float acc[4][8][4];
#pragma unroll
    for (int mi = 0; mi < 4; mi++)
#pragma unroll
        for (int ni = 0; ni < 8; ni++)
#pragma unroll
            for (int q = 0; q < 4; q++) acc[mi][ni][q] = 0.f;

    const int T = 3 * K / 64;
    load_tile(0, 0);
    load_tile(1, 64);
    load_tile(2, 128);

    const int lr16 = lane & 15;
    const int khv  = (lane >> 4) * 8;

    for (int t = 0; t < T; t++) {
        if (t < T - 2)      { CP_WAIT2(); }
        else if (t == T - 2){ CP_WAIT1(); }
        else                { CP_WAIT0(); }
        __syncthreads();

        const uint32_t sA = s0 + (t & 3) * BSTAGE;
        const uint32_t sB = sA + BMAT_A;

#pragma unroll
        for (int ks = 0; ks < 64; ks += 16) {
            uint32_t af[4][4], bf[8][2];
#pragma unroll
            for (int mi = 0; mi < 4; mi++) {
                const int row = wm * 64 + mi * 16 + lr16;
                ldm_x4(af[mi], sA + row * SSTR + (ks + khv) * 2);
            }
#pragma unroll
            for (int nh = 0; nh < 4; nh++) {
                uint32_t r[4];
                const int row = wn * 64 + nh * 16 + lr16;
                ldm_x4(r, sB + row * SSTR + (ks + khv) * 2);
                bf[2 * nh + 0][0] = r[0]; bf[2 * nh + 1][0] = r[1];
                bf[2 * nh + 0][1] = r[2]; bf[2 * nh + 1][1] = r[3];
            }
#pragma unroll
            for (int mi = 0; mi < 4; mi++)
#pragma unroll
                for (int ni = 0; ni < 8; ni++)
                    mma16816(acc[mi][ni], af[mi], bf[ni]);
        }

        if (t + 3 < T) load_tile((t + 3) & 3, (t + 3) * 64);
    }

    const int g  = lane >> 2;
    const int tt = lane & 3;
#pragma unroll
    for (int mi = 0; mi < 4; mi++) {
        const int rA = row0 + wm * 64 + mi * 16 + g;
        float* cr0 = C + (size_t)rA * ldc;
        float* cr1 = C + (size_t)(rA + 8) * ldc;
#pragma unroll
        for (int ni = 0; ni < 8; ni++) {
            const int cn = col0 + wn * 64 + ni * 8 + tt * 2;
            cr0[cn]     = acc[mi][ni][0];
            cr0[cn + 1] = acc[mi][ni][1];
            cr1[cn]     = acc[mi][ni][2];
            cr1[cn + 1] = acc[mi][ni][3];
        }
    }
}

// ---------------- 128x128 GEMM (dt_proj: K=64, bias+softplus) -----------------
#define MAT_B  (128 * SSTR)   // 18432
#define STAGE_B (2 * MAT_B)   // 36864
#define GEMM_SMEM (3 * STAGE_B)   // 110592

__global__ __launch_bounds__(256, 2)
void gemm_mma(const bf16* __restrict__ aHi, const bf16* __restrict__ aLo,
              const bf16* __restrict__ bHi, const bf16* __restrict__ bLo,
              int K, float* __restrict__ C, int ldc,
              const float* __restrict__ bias)
{
    extern __shared__ __align__(16) char smem[];

    const int tid  = threadIdx.x;
    const int wid  = tid >> 5;
    const int lane = tid & 31;
    const int wm   = wid >> 2;         // 0..1
    const int wn   = wid & 3;          // 0..3
    const int row0 = blockIdx.y * 128;
    const int col0 = blockIdx.x * 128;

    const uint32_t s0 = smem_u32(smem);

    auto load_tile = [&](int stage, int k0) {
        const bf16 *pa, *pb; int off;
        if (k0 < K)            { pa = aHi; pb = bHi; off = k0; }
        else if (k0 < 2 * K)   { pa = aLo; pb = bHi; off = k0 - K; }
        else                   { pa = aHi; pb = bLo; off = k0 - 2 * K; }
        const uint32_t sA = s0 + stage * STAGE_B;
        const uint32_t sB = sA + MAT_B;
#pragma unroll
        for (int p = 0; p < 4; p++) {
            const int cid = tid + p * 256;
            const int r = cid >> 3, c = cid & 7;
            CP_ASYNC16(sA + r * SSTR + c * 16,
                       pa + (size_t)(row0 + r) * K + off + c * 8);
            CP_ASYNC16(sB + r * SSTR + c * 16,
                       pb + (size_t)(col0 + r) * K + off + c * 8);
        }
        CP_COMMIT();
    };

    float acc[4][4][4];
#pragma unroll
    for (int mi = 0; mi < 4; mi++)
#pragma unroll
        for (int ni = 0; ni < 4; ni++)
#pragma unroll
            for (int q = 0; q < 4; q++) acc[mi][ni][q] = 0.f;

    const int T = 3 * K / 64;
    load_tile(0, 0);
    if (T > 1) load_tile(1, 64);

    const int lr16 = lane & 15;
    const int khv  = (lane >> 4) * 8;

    for (int t = 0; t < T; t++) {
        if (t == T - 1) { CP_WAIT0(); } else { CP_WAIT1(); }
        __syncthreads();

        const uint32_t sA = s0 + (t % 3) * STAGE_B;
        const uint32_t sB = sA + MAT_B;

#pragma unroll
        for (int ks = 0; ks < 64; ks += 16) {
            uint32_t af[4][4], bf[4][2];
#pragma unroll
            for (int mi = 0; mi < 4; mi++) {
                const int row = wm * 64 + mi * 16 + lr16;
                ldm_x4(af[mi], sA + row * SSTR + (ks + khv) * 2);
            }
#pragma unroll
            for (int nh = 0; nh < 2; nh++) {
                uint32_t r[4];
                const int row = wn * 32 + nh * 16 + lr16;
                ldm_x4(r, sB + row * SSTR + (ks + khv) * 2);
                bf[2 * nh + 0][0] = r[0]; bf[2 * nh + 1][0] = r[1];
                bf[2 * nh + 0][1] = r[2]; bf[2 * nh + 1][1] = r[3];
            }
#pragma unroll
            for (int mi = 0; mi < 4; mi++)
#pragma unroll
                for (int ni = 0; ni < 4; ni++)
                    mma16816(acc[mi][ni], af[mi], bf[ni]);
        }

        if (t + 2 < T) load_tile((t + 2) % 3, (t + 2) * 64);
    }

    const int g  = lane >> 2;
    const int tt = lane & 3;
#pragma unroll
    for (int mi = 0; mi < 4; mi++) {
        const int rA = row0 + wm * 64 + mi * 16 + g;
        float* cr0 = C + (size_t)rA * ldc;
        float* cr1 = C + (size_t)(rA + 8) * ldc;
#pragma unroll
        for (int ni = 0; ni < 4; ni++) {
            const int cn = col0 + wn * 32 + ni * 8 + tt * 2;
#pragma unroll
            for (int q = 0; q < 4; q++) {
                const int col = cn + (q & 1);
                float v = acc[mi][ni][q];
                v += bias[col];
                v = (v > 20.f) ? v : log1pf(expf(v));
                ((q < 2) ? cr0 : cr1)[col] = v;
            }
        }
    }
}

// ---------------- 64x128 GEMM (x_proj) with fused dt-split + BC epilogue ------
// cols 0..63  -> dtH/dtL bf16 planes [BL x 64]
// cols 64..95 -> bc fp32 [BL x 32]
#define M64_A  (64 * SSTR)         // 9216
#define M64_B  (128 * SSTR)        // 18432
#define M64_ST (M64_A + M64_B)     // 27648
#define G64_SMEM (3 * M64_ST)      // 82944

__global__ __launch_bounds__(256, 2)
void gemm_m64(const bf16* __restrict__ aHi, const bf16* __restrict__ aLo,
              const bf16* __restrict__ bHi, const bf16* __restrict__ bLo,
              int K,
              bf16* __restrict__ dtH, bf16* __restrict__ dtL,
              float* __restrict__ bc)
{
    extern __shared__ __align__(16) char smem[];

    const int tid  = threadIdx.x;
    const int wid  = tid >> 5;
    const int lane = tid & 31;
    const int wm   = wid >> 2;         // 0..1  (32 rows each)
    const int wn   = wid & 3;          // 0..3  (32 cols each)
    const int row0 = blockIdx.y * 64;

    const uint32_t s0 = smem_u32(smem);

    auto load_tile = [&](int stage, int k0) {
        const bf16 *pa, *pb; int off;
        if (k0 < K)            { pa = aHi; pb = bHi; off = k0; }
        else if (k0 < 2 * K)   { pa = aLo; pb = bHi; off = k0 - K; }
        else                   { pa = aHi; pb = bLo; off = k0 - 2 * K; }
        const uint32_t sA = s0 + stage * M64_ST;
        const uint32_t sB = sA + M64_A;
#pragma unroll
        for (int p = 0; p < 2; p++) {
            const int cid = tid + p * 256;
            const int r = cid >> 3, c = cid & 7;
            CP_ASYNC16(sA + r * SSTR + c * 16,
                       pa + (size_t)(row0 + r) * K + off + c * 8);
        }
#pragma unroll
        for (int p = 0; p < 4; p++) {
            const int cid = tid + p * 256;
            const int r = cid >> 3, c = cid & 7;
            CP_ASYNC16(sB + r * SSTR + c * 16,
                       pb + (size_t)r * K + off + c * 8);
        }
        CP_COMMIT();
    };

    float acc[2][4][4];
#pragma unroll
    for (int mi = 0; mi < 2; mi++)
#pragma unroll
        for (int ni = 0; ni < 4; ni++)
#pragma unroll
            for (int q = 0; q < 4; q++) acc[mi][ni][q] = 0.f;

    const int T = 3 * K / 64;
    load_tile(0, 0);
    load_tile(1, 64);

    const int lr16 = lane & 15;
    const int khv  = (lane >> 4) * 8;

    for (int t = 0; t < T; t++) {
        if (t == T - 1) { CP_WAIT0(); } else { CP_WAIT1(); }
        __syncthreads();

        const uint32_t sA = s0 + (t % 3) * M64_ST;
        const uint32_t sB = sA + M64_A;

#pragma unroll
        for (int ks = 0; ks < 64; ks += 16) {
            uint32_t af[2][4], bf[4][2];
#pragma unroll
            for (int mi = 0; mi < 2; mi++) {
                const int row = wm * 32 + mi * 16 + lr16;
                ldm_x4(af[mi], sA + row * SSTR + (ks + khv) * 2);
            }
#pragma unroll
            for (int nh = 0; nh < 2; nh++) {
                uint32_t r[4];
                const int row = wn * 32 + nh * 16 + lr16;
                ldm_x4(r, sB + row * SSTR + (ks + khv) * 2);
                bf[2 * nh + 0][0] = r[0]; bf[2 * nh + 1][0] = r[1];
                bf[2 * nh + 0][1] = r[2]; bf[2 * nh + 1][1] = r[3];
            }
#pragma unroll
            for (int mi = 0; mi < 2; mi++)
#pragma unroll
                for (int ni = 0; ni < 4; ni++)
                    mma16816(acc[mi][ni], af[mi], bf[ni]);
        }

        if (t + 2 < T) load_tile((t + 2) % 3, (t + 2) * 64);
    }

    const int g  = lane >> 2;
    const int tt = lane & 3;
#pragma unroll
    for (int mi = 0; mi < 2; mi++) {
        const int rA = row0 + wm * 32 + mi * 16 + g;
#pragma unroll
        for (int ni = 0; ni < 4; ni++) {
            const int cn = wn * 32 + ni * 8 + tt * 2;
#pragma unroll
            for (int q = 0; q < 4; q++) {
                const int col = cn + (q & 1);
                const int row = rA + ((q < 2) ? 0 : 8);
                const float v = acc[mi][ni][q];
                if (col < 64) {
                    const bf16 hi = __float2bfloat16(v);
                    const bf16 lo = __float2bfloat16(v - __bfloat162float(hi));
                    dtH[(size_t)row * 64 + col] = hi;
                    dtL[(size_t)row * 64 + col] = lo;
                } else if (col < 96) {
                    bc[(size_t)row * 32 + (col - 64)] = v;
                }
            }
        }
    }
}

// ---------------- fp32 -> split bf16 converters (planes) ----------------------
__global__ void cvt_act(const float* __restrict__ A, int lda, int K,
                        bf16* __restrict__ aH, bf16* __restrict__ aL)
{
    const size_t idx = (size_t)blockIdx.x * blockDim.x + threadIdx.x;
    if (idx >= (size_t)BL * K) return;
    const int m = idx / K, k = idx % K;
    const float v = A[(size_t)m * lda + k];
    const bf16 hi = __float2bfloat16(v);
    const bf16 lo = __float2bfloat16(v - __bfloat162float(hi));
    aH[idx] = hi; aL[idx] = lo;
}

__global__ void cvt_wt(const float* __restrict__ B, int K, int N, int ldb,
                       bf16* __restrict__ wH, bf16* __restrict__ wL, int Nrows)
{
    __shared__ float t[32][33];
    const int k0 = blockIdx.y * 32, n0 = blockIdx.x * 32;
    const int tx = threadIdx.x, ty = threadIdx.y;   // 32 x 8
    for (int i = ty; i < 32; i += 8) {
        const int k = k0 + i, n = n0 + tx;
        t[i][tx] = (k < K && n < N) ? B[(size_t)k * ldb + n] : 0.f;
    }
    __syncthreads();
    for (int i = ty; i < 32; i += 8) {
        const int n = n0 + i;
        if (n >= Nrows) continue;
        const int k = k0 + tx;
        const float v = t[tx][i];
        const bf16 hi = __float2bfloat16(v);
        const bf16 lo = __float2bfloat16(v - __bfloat162float(hi));
        const size_t o = (size_t)n * K + k;
        wH[o] = hi; wL[o] = lo;
    }
}

// ---------------- depthwise causal conv (k=4) + bias + SiLU, float4 ----------
__global__ void conv_silu_kernel(const float* __restrict__ xz,
                                 const float* __restrict__ w,
                                 const float* __restrict__ bias,
                                 float* __restrict__ xs,
                                 bf16* __restrict__ xsH, bf16* __restrict__ xsL)
{
    const int idx = blockIdx.x * blockDim.x + threadIdx.x;  // (bl, d4)
    if (idx >= B_ * L_ * (D_INNER / 4)) return;
    const int d4 = (idx & 511) * 4;
    const int bl = idx >> 9;
    const int l  = bl & (L_ - 1);
    const int b  = bl >> 11;

    const float* xbase = xz + (size_t)b * L_ * 4096 + d4;
    const float4 bs = *reinterpret_cast<const float4*>(bias + d4);
    float4 acc = bs;

    // weights rows d4..d4+3, each 4 taps
    const float4 wr0 = *reinterpret_cast<const float4*>(w + (d4 + 0) * 4);
    const float4 wr1 = *reinterpret_cast<const float4*>(w + (d4 + 1) * 4);
    const float4 wr2 = *reinterpret_cast<const float4*>(w + (d4 + 2) * 4);
    const float4 wr3 = *reinterpret_cast<const float4*>(w + (d4 + 3) * 4);

    if (l >= 3) {
        const float4 x = *reinterpret_cast<const float4*>(xbase + (size_t)(l - 3) * 4096);
        acc.x = fmaf(wr0.x, x.x, acc.x); acc.y = fmaf(wr1.x, x.y, acc.y);
        acc.z = fmaf(wr2.x, x.z, acc.z); acc.w = fmaf(wr3.x, x.w, acc.w);
    }
    if (l >= 2) {
        const float4 x = *reinterpret_cast<const float4*>(xbase + (size_t)(l - 2) * 4096);
        acc.x = fmaf(wr0.y, x.x, acc.x); acc.y = fmaf(wr1.y, x.y, acc.y);
        acc.z = fmaf(wr2.y, x.z, acc.z); acc.w = fmaf(wr3.y, x.w, acc.w);
    }
    if (l >= 1) {
        const float4 x = *reinterpret_cast<const float4*>(xbase + (size_t)(l - 1) * 4096);
        acc.x = fmaf(wr0.z, x.x, acc.x); acc.y = fmaf(wr1.z, x.y, acc.y);
        acc.z = fmaf(wr2.z, x.z, acc.z); acc.w = fmaf(wr3.z, x.w, acc.w);
    }
    {
        const float4 x = *reinterpret_cast<const float4*>(xbase + (size_t)l * 4096);
        acc.x = fmaf(wr0.w, x.x, acc.x); acc.y = fmaf(wr1.w, x.y, acc.y);
        acc.z = fmaf(wr2.w, x.z, acc.z); acc.w = fmaf(wr3.w, x.w, acc.w);
    }

    float4 s;
    s.x = acc.x * (1.f / (1.f + __expf(-acc.x)));
    s.y = acc.y * (1.f / (1.f + __expf(-acc.y)));
    s.z = acc.z * (1.f / (1.f + __expf(-acc.z)));
    s.w = acc.w * (1.f / (1.f + __expf(-acc.w)));

    const size_t o = (size_t)bl * 2048 + d4;
    *reinterpret_cast<float4*>(xs + o) = s;

    bf16 h0 = __float2bfloat16(s.x), h1 = __float2bfloat16(s.y);
    bf16 h2 = __float2bfloat16(s.z), h3 = __float2bfloat16(s.w);
    bf16 l0 = __float2bfloat16(s.x - __bfloat162float(h0));
    bf16 l1 = __float2bfloat16(s.y - __bfloat162float(h1));
    bf16 l2 = __float2bfloat16(s.z - __bfloat162float(h2));
    bf16 l3 = __float2bfloat16(s.w - __bfloat162float(h3));
    __nv_bfloat162* pH = reinterpret_cast<__nv_bfloat162*>(xsH + o);
    __nv_bfloat162* pL = reinterpret_cast<__nv_bfloat162*>(xsL + o);
    pH[0] = __nv_bfloat162(h0, h1); pH[1] = __nv_bfloat162(h2, h3);
    pL[0] = __nv_bfloat162(l0, l1); pL[1] = __nv_bfloat162(l2, l3);
}

// ---------------- selective scan v3: short serial chain + batched shfl -------
__global__ __launch_bounds__(256) void scan_kernel(
    const float* __restrict__ delta, const float* __restrict__ bc,
    const float* __restrict__ xs, const float* __restrict__ xz,
    const float* __restrict__ A_log, const float* __restrict__ Dvec,
    const float* __restrict__ hiddens,
    bf16* __restrict__ yH, bf16* __restrict__ yL)
{
    __shared__ float sdt[16][16];
    __shared__ float sxv[16][16];
    __shared__ float srv[16][16];
    __shared__ float sy [16][16];
    __shared__ float sBC[16][32];      // cols 0..15 = B, 16..31 = C

    const int tid = threadIdx.x;
    const int n   = tid & 15;
    const int gl  = tid >> 4;
    const int g   = blockIdx.x * 16 + gl;
    const int b   = g >> 11;
    const int d   = g & (D_INNER - 1);
    const int d0  = d - gl;

    const float a = -__expf(A_log[d * D_STATE + n]);
    float h = hiddens[((size_t)b * D_INNER + d) * D_STATE + n];
    const float Dd = Dvec[d];

    const float* bcp = bc + (size_t)b * L_ * 32;

    const int lr = tid >> 4, lc = tid & 15;
    const float* dltS = delta + (size_t)b * L_ * 2048 + d0 + lc;
    const float* xsS  = xs    + (size_t)b * L_ * 2048 + d0 + lc;
    const float* rvS  = xz    + (size_t)b * L_ * 4096 + 2048 + d0 + lc;
    bf16* yHS = yH + (size_t)b * L_ * 2048 + d0 + lc;
    bf16* yLS = yL + (size_t)b * L_ * 2048 + d0 + lc;
    const int br = tid >> 5, bcc = tid & 31;

    for (int l0 = 0; l0 < L_; l0 += 16) {
        sdt[lr][lc] = dltS[(size_t)(l0 + lr) * 2048];
        sxv[lr][lc] = xsS [(size_t)(l0 + lr) * 2048];
        srv[lr][lc] = rvS [(size_t)(l0 + lr) * 4096];
        sBC[br    ][bcc] = bcp[(l0 + br    ) * 32 + bcc];
        sBC[br + 8][bcc] = bcp[(l0 + br + 8) * 32 + bcc];
        __syncthreads();

        // phase 1: precompute dA[j], t[j]  (independent, ILP-rich)
        float dA[16], tv[16];
#pragma unroll
        for (int j = 0; j < 16; j++) {
            dA[j] = __expf(sdt[j][gl] * a);
            tv[j] = sdt[j][gl] * sBC[j][n] * sxv[j][gl];
        }
        // phase 2: serial recurrence — 16 chained FFMAs only
        float hC[16];
#pragma unroll
        for (int j = 0; j < 16; j++) {
            h = fmaf(dA[j], h, tv[j]);
            hC[j] = h * sBC[j][16 + n];
        }
        // phase 3: batched reductions (independent across j)
#pragma unroll
        for (int j = 0; j < 16; j++) {
            float s = hC[j];
            s += __shfl_xor_sync(0xffffffffu, s, 1);
            s += __shfl_xor_sync(0xffffffffu, s, 2);
            s += __shfl_xor_sync(0xffffffffu, s, 4);
            s += __shfl_xor_sync(0xffffffffu, s, 8);
            if (n == 0) {
                float y = fmaf(sxv[j][gl], Dd, s);
                const float rv = srv[j][gl];
                y *= rv * (1.f / (1.f + __expf(-rv)));
                sy[j][gl] = y;
            }
        }
        __syncthreads();

        {
            const float y = sy[lr][lc];
            const bf16 hi = __float2bfloat16(y);
            const bf16 lo = __float2bfloat16(y - __bfloat162float(hi));
            yHS[(size_t)(l0 + lr) * 2048] = hi;
            yLS[(size_t)(l0 + lr) * 2048] = lo;
        }
    }
}

// ---------------- launch ------------------------------------------------------
extern "C" void kernel_launch(void* const* d_in, const int* in_sizes, int n_in,
                              void* d_out, int out_size)
{
    const float* u          = (const float*)d_in[0];
    const float* hiddens    = (const float*)d_in[1];
    const float* in_proj_w  = (const float*)d_in[2];
    const float* conv_w     = (const float*)d_in[3];
    const float* conv_b     = (const float*)d_in[4];
    const float* x_proj_w   = (const float*)d_in[5];
    const float* dt_proj_w  = (const float*)d_in[6];
    const float* dt_proj_b  = (const float*)d_in[7];
    const float* A_log      = (const float*)d_in[8];
    const float* Dvec       = (const float*)d_in[9];
    const float* out_proj_w = (const float*)d_in[10];
    float* out = (float*)d_out;

    float *xz, *xs, *bcb, *delta;
    bf16 *uH, *uL, *xsH, *xsL, *dtH, *dtL, *yH, *yL;
    bf16 *wiH, *wiL, *wxH, *wxL, *wdH, *wdL, *woH, *woL;
    cudaGetSymbolAddress((void**)&xz, g_xz);
    cudaGetSymbolAddress((void**)&xs, g_xs);
    cudaGetSymbolAddress((void**)&bcb, g_bc);
    cudaGetSymbolAddress((void**)&delta, g_delta);
    cudaGetSymbolAddress((void**)&uH, g_uH);   cudaGetSymbolAddress((void**)&uL, g_uL);
    cudaGetSymbolAddress((void**)&xsH, g_xsH); cudaGetSymbolAddress((void**)&xsL, g_xsL);
    cudaGetSymbolAddress((void**)&dtH, g_dtH); cudaGetSymbolAddress((void**)&dtL, g_dtL);
    cudaGetSymbolAddress((void**)&yH, g_yH);   cudaGetSymbolAddress((void**)&yL, g_yL);
    cudaGetSymbolAddress((void**)&wiH, g_wiH); cudaGetSymbolAddress((void**)&wiL, g_wiL);
    cudaGetSymbolAddress((void**)&wxH, g_wxH); cudaGetSymbolAddress((void**)&wxL, g_wxL);
    cudaGetSymbolAddress((void**)&wdH, g_wdH); cudaGetSymbolAddress((void**)&wdL, g_wdL);
    cudaGetSymbolAddress((void**)&woH, g_woH); cudaGetSymbolAddress((void**)&woL, g_woL);

    cudaFuncSetAttribute(gemm_big, cudaFuncAttributeMaxDynamicSharedMemorySize, BIG_SMEM);
    cudaFuncSetAttribute(gemm_mma, cudaFuncAttributeMaxDynamicSharedMemorySize, GEMM_SMEM);
    cudaFuncSetAttribute(gemm_m64, cudaFuncAttributeMaxDynamicSharedMemorySize, G64_SMEM);

    const dim3 tb(32, 8);

    // weight conversions (transposed, hi/lo planes)
    cvt_wt<<<dim3(4096 / 32, 1024 / 32), tb>>>(in_proj_w, 1024, 4096, 4096, wiH, wiL, 4096);
    cvt_wt<<<dim3(128 / 32, 2048 / 32), tb>>>(x_proj_w, 2048, 96, 96, wxH, wxL, 128);
    cvt_wt<<<dim3(2048 / 32, 64 / 32), tb>>>(dt_proj_w, 64, 2048, 2048, wdH, wdL, 2048);
    cvt_wt<<<dim3(1024 / 32, 2048 / 32), tb>>>(out_proj_w, 2048, 1024, 1024, woH, woL, 1024);

    // u -> planes
    cvt_act<<<(int)(((size_t)BL * 1024 + 255) / 256), 256>>>(u, 1024, 1024, uH, uL);

    // 1) in_proj: xz[8192,4096], K=1024 (T=48)
    gemm_big<<<dim3(4096 / 128, BL / 256), 256, BIG_SMEM>>>(
        uH, uL, wiH, wiL, 1024, xz, 4096);

    // 2) conv + bias + silu -> xs (fp32) + xsH/xsL
    conv_silu_kernel<<<(B_ * L_ * (D_INNER / 4) + 255) / 256, 256>>>(
        xz, conv_w, conv_b, xs, xsH, xsL);

    // 3) x_proj: K=2048 (T=96), fused dt-split + BC epilogue, 128 CTAs
    gemm_m64<<<dim3(1, BL / 64), 256, G64_SMEM>>>(
        xsH, xsL, wxH, wxL, 2048, dtH, dtL, bcb);

    // 4) dt_proj + softplus: delta[8192,2048], K=64 (T=3)
    gemm_mma<<<dim3(2048 / 128, BL / 128), 256, GEMM_SMEM>>>(
        dtH, dtL, wdH, wdL, 64, delta, 2048, dt_proj_b);

    // 5) selective scan + D skip + silu(res) gating -> yH/yL
    scan_kernel<<<(B_ * D_INNER * D_STATE) / 256, 256>>>(
        delta, bcb, xs, xz, A_log, Dvec, hiddens, yH, yL);

    // 6) out_proj: out[8192,1024], K=2048 (T=96)
    gemm_big<<<dim3(1024 / 128, BL / 256), 256, BIG_SMEM>>>(
        yH, yL, woH, woL, 2048, out, 1024);
}